// round 2
// baseline (speedup 1.0000x reference)
#include <cuda_runtime.h>
#include <cstdint>

#define BB 64
#define TT 1500
#define FF 36
#define HH 512
#define HS 8
#define NN 32
#define GRID 128
#define NTHREADS 256

// ---------------- device globals (scratch; no allocs allowed) ----------------
__device__ float g_xg0p[(size_t)TT * 64 * BB * NN];   // 786 MB: x@W_ih0^T + biases, [t][cta][b][n]
__device__ float g_wp1[64 * NN * 512];                // layer1 W_hh packed [cta][n][k], tf32-rounded
__device__ float g_wp2[64 * NN * 1024];               // layer2 [W_ih1;W_hh1] packed [cta][n][k]
__device__ float g_bias2[64 * NN];
__device__ float g_h1[2][BB * HH];                    // double-buffered hidden state, layer 1
__device__ float g_h2[2][BB * HH];                    // layer 2
__device__ unsigned g_bar;

// ---------------- helpers ----------------
__device__ __forceinline__ float tf32r(float x) {
    uint32_t u;
    asm("cvt.rna.tf32.f32 %0, %1;" : "=r"(u) : "f"(x));
    return __uint_as_float(u);
}

__device__ __forceinline__ void mma8(float* d, uint32_t a0, uint32_t a1, uint32_t a2, uint32_t a3,
                                     uint32_t b0, uint32_t b1) {
    asm volatile(
        "mma.sync.aligned.m16n8k8.row.col.f32.tf32.tf32.f32 "
        "{%0,%1,%2,%3},{%4,%5,%6,%7},{%8,%9},{%0,%1,%2,%3};\n"
        : "+f"(d[0]), "+f"(d[1]), "+f"(d[2]), "+f"(d[3])
        : "r"(a0), "r"(a1), "r"(a2), "r"(a3), "r"(b0), "r"(b1));
}

__device__ __forceinline__ void grid_bar(unsigned target) {
    __syncthreads();
    if (threadIdx.x == 0) {
        unsigned* p = &g_bar;
        asm volatile("red.release.gpu.global.add.u32 [%0], 1;" ::"l"(p) : "memory");
        unsigned v;
        do {
            asm volatile("ld.acquire.gpu.global.u32 %0, [%1];" : "=r"(v) : "l"(p) : "memory");
        } while (v < target);
    }
    __syncthreads();
}

__device__ __forceinline__ float sigm(float x) { return 1.f / (1.f + __expf(-x)); }

// ---------------- setup kernels ----------------
__global__ void reset_kernel() { g_bar = 0u; }

__global__ void pack_kernel(const float* __restrict__ Whh0, const float* __restrict__ Wih1,
                            const float* __restrict__ Whh1, const float* __restrict__ bih1,
                            const float* __restrict__ bhh1) {
    int c = blockIdx.x;
    if (c < 64) {
        for (int idx = threadIdx.x; idx < NN * 512; idx += NTHREADS) {
            int n = idx >> 9, k = idx & 511;
            int row = (n >> 3) * HH + c * HS + (n & 7);
            g_wp1[(c * NN + n) * 512 + k] = tf32r(Whh0[row * HH + k]);
        }
    } else {
        int cc = c - 64;
        for (int idx = threadIdx.x; idx < NN * 1024; idx += NTHREADS) {
            int n = idx >> 10, k = idx & 1023;
            int row = (n >> 3) * HH + cc * HS + (n & 7);
            float v = (k < 512) ? Wih1[row * HH + k] : Whh1[row * HH + (k - 512)];
            g_wp2[(cc * NN + n) * 1024 + k] = tf32r(v);
        }
        if (threadIdx.x < NN) {
            int n = threadIdx.x;
            int row = (n >> 3) * HH + cc * HS + (n & 7);
            g_bias2[cc * NN + n] = bih1[row] + bhh1[row];
        }
    }
}

// xg0p[t][c][b][n] = dot(x[b,t,:], W_ih0[row(c,n),:]) + b_ih0 + b_hh0
__global__ void xg0_kernel(const float* __restrict__ x, const float* __restrict__ Wih0,
                           const float* __restrict__ bih0, const float* __restrict__ bhh0) {
    __shared__ float xs[64][37];
    __shared__ float ws[32][37];
    __shared__ float bs[32];
    int t = blockIdx.x >> 6;
    int c = blockIdx.x & 63;
    for (int i = threadIdx.x; i < 64 * FF; i += NTHREADS) {
        int b = i / FF, f = i - b * FF;
        xs[b][f] = x[((size_t)b * TT + t) * FF + f];
    }
    for (int i = threadIdx.x; i < 32 * FF; i += NTHREADS) {
        int n = i / FF, f = i - n * FF;
        int row = (n >> 3) * HH + c * HS + (n & 7);
        ws[n][f] = Wih0[row * FF + f];
    }
    if (threadIdx.x < 32) {
        int n = threadIdx.x;
        int row = (n >> 3) * HH + c * HS + (n & 7);
        bs[n] = bih0[row] + bhh0[row];
    }
    __syncthreads();
    int n = threadIdx.x & 31;
    int b0 = threadIdx.x >> 5;
    for (int j = 0; j < 8; j++) {
        int b = b0 * 8 + j;
        float acc = bs[n];
#pragma unroll
        for (int f = 0; f < FF; f++) acc += xs[b][f] * ws[n][f];
        g_xg0p[(((size_t)t * 64 + c) * BB + b) * NN + n] = acc;
    }
}

// ---------------- persistent fused 2-layer LSTM ----------------
// smem: Wsm 32x1028 | Asm 64x260 | Gsm 64x33 | Csm 64x8  = 52160 floats = 208640 B
#define SMEM_BYTES (208640)

__global__ void __launch_bounds__(NTHREADS, 1) lstm_kernel() {
    extern __shared__ float smem[];
    float* Wsm = smem;
    float* Asm = smem + 32 * 1028;
    float* Gsm = Asm + 64 * 260;
    float* Csm = Gsm + 64 * 33;

    const int cta = blockIdx.x;
    const int layer = (cta >= 64) ? 1 : 0;
    const int c = layer ? (cta - 64) : cta;
    const int KT = layer ? 1024 : 512;
    const int WST = KT + 4;  // stride % 32 == 4 -> conflict-free fragment loads
    const int tid = threadIdx.x;

    // load this CTA's weight slice to smem (persists across all steps)
    {
        const float* wp = layer ? (g_wp2 + c * NN * 1024) : (g_wp1 + c * NN * 512);
        for (int i = tid * 4; i < NN * KT; i += NTHREADS * 4) {
            int n = i / KT, k = i - n * KT;
            float4 v = *(const float4*)(wp + i);
            *(float4*)(Wsm + n * WST + k) = v;
        }
    }
    // zero parity-1 of my h slice + cell state
    {
        float* hb = layer ? g_h2[1] : g_h1[1];
        for (int i = tid; i < BB * HS; i += NTHREADS) {
            int b = i >> 3, hl = i & 7;
            hb[b * HH + c * HS + hl] = 0.f;
            Csm[i] = 0.f;
        }
    }
    unsigned target = GRID;
    grid_bar(target);

    const int w = tid >> 5, lane = tid & 31;
    const int gid = lane >> 2, tig = lane & 3;
    const int mt = w & 3;            // M tile (16 rows) of batch
    const int nb = (w >> 2) * 2;     // first of 2 N tiles (8 cols each)
    const int nchunk = KT >> 8;

    for (int s = 0; s <= TT; s++) {
        const int t = layer ? (s - 1) : s;
        const bool active = layer ? (s >= 1) : (s < TT);
        if (active) {
            float acc0[4] = {0.f, 0.f, 0.f, 0.f};
            float acc1[4] = {0.f, 0.f, 0.f, 0.f};
            for (int ch = 0; ch < nchunk; ch++) {
                const float* src;
                int k0;
                if (!layer)      { src = g_h1[(t & 1) ^ 1]; k0 = ch << 8; }
                else if (ch < 2) { src = g_h1[t & 1];       k0 = ch << 8; }   // x_t = h1[t]
                else             { src = g_h2[(t & 1) ^ 1]; k0 = (ch - 2) << 8; }
                __syncthreads();
                {   // stage A chunk (64 x 256) into smem, L2-only loads (L1 may be stale)
                    int b = tid >> 2, co = (tid & 3) << 6;
                    const float4* sp = (const float4*)(src + b * HH + k0 + co);
                    float4* dp = (float4*)(Asm + b * 260 + co);
#pragma unroll
                    for (int j = 0; j < 16; j++) dp[j] = __ldcg(sp + j);
                }
                __syncthreads();
                const float* Arow0 = Asm + (mt * 16 + gid) * 260 + tig;
                const float* Brow0 = Wsm + (nb * 8 + gid) * WST + (ch << 8) + tig;
                const float* Brow1 = Brow0 + 8 * WST;
#pragma unroll 8
                for (int kt = 0; kt < 32; kt++) {
                    uint32_t a0 = __float_as_uint(Arow0[kt * 8]);
                    uint32_t a1 = __float_as_uint(Arow0[kt * 8 + 8 * 260]);
                    uint32_t a2 = __float_as_uint(Arow0[kt * 8 + 4]);
                    uint32_t a3 = __float_as_uint(Arow0[kt * 8 + 8 * 260 + 4]);
                    uint32_t b0 = __float_as_uint(Brow0[kt * 8]);
                    uint32_t b1 = __float_as_uint(Brow0[kt * 8 + 4]);
                    uint32_t b2 = __float_as_uint(Brow1[kt * 8]);
                    uint32_t b3 = __float_as_uint(Brow1[kt * 8 + 4]);
                    mma8(acc0, a0, a1, a2, a3, b0, b1);
                    mma8(acc1, a0, a1, a2, a3, b2, b3);
                }
            }
            {   // accum -> gates smem
                int r0 = mt * 16 + gid;
                int c0 = nb * 8 + tig * 2;
                Gsm[r0 * 33 + c0] = acc0[0];
                Gsm[r0 * 33 + c0 + 1] = acc0[1];
                Gsm[(r0 + 8) * 33 + c0] = acc0[2];
                Gsm[(r0 + 8) * 33 + c0 + 1] = acc0[3];
                int c1 = c0 + 8;
                Gsm[r0 * 33 + c1] = acc1[0];
                Gsm[r0 * 33 + c1 + 1] = acc1[1];
                Gsm[(r0 + 8) * 33 + c1] = acc1[2];
                Gsm[(r0 + 8) * 33 + c1 + 1] = acc1[3];
            }
            __syncthreads();
            // elementwise LSTM cell for my 8 hidden units x 64 batches
            float* dst = layer ? g_h2[t & 1] : g_h1[t & 1];
#pragma unroll
            for (int rep = 0; rep < 2; rep++) {
                int it = tid + rep * NTHREADS;
                int b = it >> 3, hl = it & 7;
                float pi, pf, pg, po;
                if (!layer) {
                    const float* xg = g_xg0p + (((size_t)t * 64 + c) * BB + b) * NN;
                    pi = Gsm[b * 33 + hl] + xg[hl];
                    pf = Gsm[b * 33 + 8 + hl] + xg[8 + hl];
                    pg = Gsm[b * 33 + 16 + hl] + xg[16 + hl];
                    po = Gsm[b * 33 + 24 + hl] + xg[24 + hl];
                } else {
                    const float* bb2 = g_bias2 + c * NN;
                    pi = Gsm[b * 33 + hl] + bb2[hl];
                    pf = Gsm[b * 33 + 8 + hl] + bb2[8 + hl];
                    pg = Gsm[b * 33 + 16 + hl] + bb2[16 + hl];
                    po = Gsm[b * 33 + 24 + hl] + bb2[24 + hl];
                }
                float iv = sigm(pi);
                float fv = sigm(pf);
                float gv = tanhf(pg);
                float ov = sigm(po);
                float cv = fv * Csm[it] + iv * gv;
                Csm[it] = cv;
                dst[b * HH + c * HS + hl] = tf32r(ov * tanhf(cv));
            }
        }
        target += GRID;
        grid_bar(target);
    }
}

// ---------------- final projection ----------------
__global__ void out_kernel(const float* __restrict__ Wout, const float* __restrict__ bout,
                           float* __restrict__ out) {
    int idx = blockIdx.x * NTHREADS + threadIdx.x;  // 4096 = 64 x 64
    int b = idx >> 6, o = idx & 63;
    const float* h = g_h2[(TT - 1) & 1] + b * HH;   // parity of last written step
    const float* wr = Wout + o * HH;
    float acc = bout[o];
#pragma unroll 8
    for (int k = 0; k < HH; k++) acc += h[k] * wr[k];
    out[b * 64 + o] = acc;
}

// ---------------- launch ----------------
extern "C" void kernel_launch(void* const* d_in, const int* in_sizes, int n_in,
                              void* d_out, int out_size) {
    const float* x    = (const float*)d_in[0];
    const float* Wih0 = (const float*)d_in[1];
    const float* Whh0 = (const float*)d_in[2];
    const float* bih0 = (const float*)d_in[3];
    const float* bhh0 = (const float*)d_in[4];
    const float* Wih1 = (const float*)d_in[5];
    const float* Whh1 = (const float*)d_in[6];
    const float* bih1 = (const float*)d_in[7];
    const float* bhh1 = (const float*)d_in[8];
    const float* Wout = (const float*)d_in[9];
    const float* bout = (const float*)d_in[10];
    float* out = (float*)d_out;

    cudaFuncSetAttribute(lstm_kernel, cudaFuncAttributeMaxDynamicSharedMemorySize, SMEM_BYTES);

    reset_kernel<<<1, 1>>>();
    pack_kernel<<<128, NTHREADS>>>(Whh0, Wih1, Whh1, bih1, bhh1);
    xg0_kernel<<<TT * 64, NTHREADS>>>(x, Wih0, bih0, bhh0);
    lstm_kernel<<<GRID, NTHREADS, SMEM_BYTES>>>();
    out_kernel<<<16, NTHREADS>>>(Wout, bout, out);
}

// round 3
// speedup vs baseline: 3.3230x; 3.3230x over previous
#include <cuda_runtime.h>
#include <cstdint>

#define BB 64
#define TT 1500
#define FF 36
#define HH 512
#define NT 128          // threads per lstm CTA (4 warps)
#define GRID 128

// ---------------- device globals ----------------
__device__ float g_xg0p[(size_t)TT * 64 * 128 * 16];  // 786MB: per-consumer-thread acc-init [t][c][tau][nt*4+p]
__device__ float g_wf1[64 * 16384];                   // layer1 B-fragments [c][kt64][p2][lane32][4]
__device__ float g_wf2[64 * 32768];                   // layer2 B-fragments [c][kt128][p2][lane32][4]
__device__ float g_b2p[64 * 128 * 8];                 // layer2 bias per consumer thread [c][tau][nt*2+jj]
__device__ float g_h1f[4][32768];                     // h1 ring, fragment layout [buf][kt64][mt4][lane32][4]
__device__ float g_h2f[2][32768];                     // h2 ring
__device__ unsigned g_f1[TT + 2];
__device__ unsigned g_f2[TT + 2];

// ---------------- helpers ----------------
__device__ __forceinline__ float tf32r(float x) {
    uint32_t u;
    asm("cvt.rna.tf32.f32 %0, %1;" : "=r"(u) : "f"(x));
    return __uint_as_float(u);
}
__device__ __forceinline__ float tanha(float x) {
    float y;
    asm("tanh.approx.f32 %0, %1;" : "=f"(y) : "f"(x));
    return y;
}
__device__ __forceinline__ float sigm(float x) { return fmaf(tanha(0.5f * x), 0.5f, 0.5f); }

__device__ __forceinline__ void mma8(float* d, float4 a, float b0, float b1) {
    asm volatile(
        "mma.sync.aligned.m16n8k8.row.col.f32.tf32.tf32.f32 "
        "{%0,%1,%2,%3},{%4,%5,%6,%7},{%8,%9},{%0,%1,%2,%3};\n"
        : "+f"(d[0]), "+f"(d[1]), "+f"(d[2]), "+f"(d[3])
        : "r"(__float_as_uint(a.x)), "r"(__float_as_uint(a.y)),
          "r"(__float_as_uint(a.z)), "r"(__float_as_uint(a.w)),
          "r"(__float_as_uint(b0)), "r"(__float_as_uint(b1)));
}

__device__ __forceinline__ void waitflag(const unsigned* p, unsigned tgt) {
    unsigned v;
    do {
        asm volatile("ld.acquire.gpu.global.u32 %0, [%1];" : "=r"(v) : "l"(p) : "memory");
    } while (v < tgt);
}

// 64 k-tiles: A fragments direct from gmem (fragment layout), B fragments from smem
__device__ __forceinline__ void gemm64(float acc[4][4], const float4* __restrict__ Ap,
                                       const float4* __restrict__ Bp, int lane) {
    float4 aq[8];
#pragma unroll
    for (int i = 0; i < 8; i++) aq[i] = __ldcg(Ap + i * 128);
#pragma unroll 8
    for (int kt = 0; kt < 64; kt++) {
        float4 av = aq[kt & 7];
        float4 b0 = Bp[kt * 64 + lane];
        float4 b1 = Bp[kt * 64 + 32 + lane];
        if (kt < 56) aq[kt & 7] = __ldcg(Ap + (kt + 8) * 128);
        mma8(acc[0], av, b0.x, b0.y);
        mma8(acc[1], av, b0.z, b0.w);
        mma8(acc[2], av, b1.x, b1.y);
        mma8(acc[3], av, b1.z, b1.w);
    }
}

// ---------------- setup kernels ----------------
__global__ void reset_kernel() {
    int idx = blockIdx.x * 256 + threadIdx.x;
    if (idx < TT + 2) {
        g_f1[idx] = (idx == 0) ? 64u : 0u;
        g_f2[idx] = (idx == 0) ? 64u : 0u;
    }
    if (idx < 32768) {
        g_h1f[3][idx] = 0.f;  // h1[-1] buffer ((-1)&3 = 3)
        g_h2f[1][idx] = 0.f;  // h2[-1] buffer ((-1)&1 = 1)
    }
}

__global__ void pack_kernel(const float* __restrict__ Whh0, const float* __restrict__ Wih1,
                            const float* __restrict__ Whh1, const float* __restrict__ bih1,
                            const float* __restrict__ bhh1) {
    int cb = blockIdx.x;
    if (cb < 64) {
        int c = cb;
        float* dst = g_wf1 + c * 16384;
        for (int idx = threadIdx.x; idx < 16384; idx += 256) {
            int e = idx & 3, lane = (idx >> 2) & 31, p = (idx >> 7) & 1, kt = idx >> 8;
            int gid = lane >> 2, tig = lane & 3;
            int nt = p * 2 + (e >> 1);
            int k = kt * 8 + tig + 4 * (e & 1);
            int row = nt * HH + c * 8 + gid;
            dst[idx] = tf32r(Whh0[row * HH + k]);
        }
    } else {
        int c = cb - 64;
        float* dst = g_wf2 + c * 32768;
        for (int idx = threadIdx.x; idx < 32768; idx += 256) {
            int e = idx & 3, lane = (idx >> 2) & 31, p = (idx >> 7) & 1, kt = idx >> 8;
            int gid = lane >> 2, tig = lane & 3;
            int nt = p * 2 + (e >> 1);
            int ks = tig + 4 * (e & 1);
            int row = nt * HH + c * 8 + gid;
            float v = (kt < 64) ? Wih1[row * HH + kt * 8 + ks]
                                : Whh1[row * HH + (kt - 64) * 8 + ks];
            dst[idx] = tf32r(v);
        }
        for (int idx = threadIdx.x; idx < 128 * 8; idx += 256) {
            int tau = idx >> 3, q = idx & 7;
            int nt = q >> 1, jj = q & 1;
            int tig = tau & 3;
            int row = nt * HH + c * 8 + tig * 2 + jj;
            g_b2p[(c * 128 + tau) * 8 + q] = bih1[row] + bhh1[row];
        }
    }
}

// acc-init values for layer1: dot(x[b,t,:], W_ih0[row,:]) + b_ih0 + b_hh0, consumer-thread layout
__global__ void xg0_kernel(const float* __restrict__ x, const float* __restrict__ Wih0,
                           const float* __restrict__ bih0, const float* __restrict__ bhh0) {
    __shared__ float xs[64][37];
    __shared__ float ws[32][37];
    __shared__ float bsm[32];
    int t = blockIdx.x >> 6, c = blockIdx.x & 63;
    for (int i = threadIdx.x; i < 64 * FF; i += 256) {
        int b = i / FF, f = i - b * FF;
        xs[b][f] = x[((size_t)b * TT + t) * FF + f];
    }
    for (int i = threadIdx.x; i < 32 * FF; i += 256) {
        int r = i / FF, f = i - r * FF;
        int row = (r >> 3) * HH + c * 8 + (r & 7);
        ws[r][f] = Wih0[row * FF + f];
    }
    if (threadIdx.x < 32) {
        int r = threadIdx.x;
        int row = (r >> 3) * HH + c * 8 + (r & 7);
        bsm[r] = bih0[row] + bhh0[row];
    }
    __syncthreads();
    int tau = threadIdx.x & 127, half = threadIdx.x >> 7;
    int mt = tau >> 5, lane = tau & 31, gid = lane >> 2, tig = lane & 3;
    float* outp = g_xg0p + (((size_t)t * 64 + c) * 128 + tau) * 16 + half * 8;
#pragma unroll
    for (int q = 0; q < 2; q++) {
        int nt = half * 2 + q;
#pragma unroll
        for (int p = 0; p < 4; p++) {
            int b = mt * 16 + gid + 8 * (p >> 1);
            int hl = tig * 2 + (p & 1);
            int r = nt * 8 + hl;
            float acc = bsm[r];
#pragma unroll
            for (int f = 0; f < FF; f++) acc = fmaf(xs[b][f], ws[r][f], acc);
            outp[q * 4 + p] = acc;
        }
    }
}

// ---------------- persistent 2-layer LSTM ----------------
#define SMEM_BYTES 131072

__global__ void __launch_bounds__(NT, 1) lstm_kernel() {
    extern __shared__ float4 Bs4[];
    const int cta = blockIdx.x;
    const int layer = cta >> 6;
    const int c = cta & 63;
    const int tid = threadIdx.x;
    const int mt = tid >> 5, lane = tid & 31;
    const int tig = lane & 3;
    const int gid = lane >> 2;

    {   // weights -> smem (linear copy, already fragment-packed)
        const float4* wsrc = (const float4*)(layer ? (g_wf2 + c * 32768) : (g_wf1 + c * 16384));
        int tot = layer ? 8192 : 4096;
        for (int i = tid; i < tot; i += NT) Bs4[i] = wsrc[i];
    }
    float bias[16];
    if (layer) {
        const float* bp = g_b2p + (c * 128 + tid) * 8;
#pragma unroll
        for (int nt = 0; nt < 4; nt++) {
            float2 v = *(const float2*)(bp + nt * 2);
            bias[nt * 4 + 0] = v.x; bias[nt * 4 + 1] = v.y;
            bias[nt * 4 + 2] = v.x; bias[nt * 4 + 3] = v.y;
        }
    }
    float cst[4] = {0.f, 0.f, 0.f, 0.f};
    __syncthreads();

    for (int t = 0; t < TT; t++) {
        float acc[4][4];
        if (!layer) {
            // prefetch acc-init (DRAM) before the spin — fully hidden
            float4 xg[4];
            const float4* xp = (const float4*)(g_xg0p + (((size_t)t * 64 + c) * 128 + tid) * 16);
#pragma unroll
            for (int nt = 0; nt < 4; nt++) xg[nt] = __ldcg(xp + nt);
            if (t >= 4) waitflag(g_f2 + (t - 3), 64);   // ring-overwrite guard (lag <= 3)
            waitflag(g_f1 + t, 64);                     // h1[t-1] ready
#pragma unroll
            for (int nt = 0; nt < 4; nt++) {
                acc[nt][0] = xg[nt].x; acc[nt][1] = xg[nt].y;
                acc[nt][2] = xg[nt].z; acc[nt][3] = xg[nt].w;
            }
            const float4* Ap = (const float4*)g_h1f + ((t - 1) & 3) * 8192 + mt * 32 + lane;
            gemm64(acc, Ap, Bs4, lane);
        } else {
#pragma unroll
            for (int q = 0; q < 16; q++) acc[q >> 2][q & 3] = bias[q];
            waitflag(g_f2 + t, 64);                     // h2[t-1] ready (own group)
            const float4* Ap2 = (const float4*)g_h2f + ((t - 1) & 1) * 8192 + mt * 32 + lane;
            gemm64(acc, Ap2, Bs4 + 64 * 64, lane);      // W_hh1 half, overlaps layer1's step t
            waitflag(g_f1 + t + 1, 64);                 // h1[t] ready
            const float4* Ap1 = (const float4*)g_h1f + (t & 3) * 8192 + mt * 32 + lane;
            gemm64(acc, Ap1, Bs4, lane);                // W_ih1 half
        }
        // elementwise entirely in registers; write h in consumer fragment layout
        float* slab = (layer ? (float*)g_h2f + (t & 1) * 32768
                             : (float*)g_h1f + (t & 3) * 32768) + c * 512 + mt * 128;
#pragma unroll
        for (int p = 0; p < 4; p++) {
            float ig = sigm(acc[0][p]);
            float fg = sigm(acc[1][p]);
            float gg = tanha(acc[2][p]);
            float og = sigm(acc[3][p]);
            float cv = fmaf(fg, cst[p], ig * gg);
            cst[p] = cv;
            float hv = og * tanha(cv);
            int hl = tig * 2 + (p & 1);
            int tigp = hl & 3;
            int v = 2 * (hl >> 2) + (p >> 1);
            slab[(gid * 4 + tigp) * 4 + v] = tf32r(hv);
        }
        __syncthreads();
        if (tid == 0) {
            unsigned* fp = (layer ? g_f2 : g_f1) + t + 1;
            asm volatile("red.release.gpu.global.add.u32 [%0], 1;" ::"l"(fp) : "memory");
        }
    }
}

// ---------------- final projection ----------------
__global__ void out_kernel(const float* __restrict__ Wout, const float* __restrict__ bout,
                           float* __restrict__ out) {
    __shared__ float hs[512];
    int b = blockIdx.x;
    for (int k = threadIdx.x; k < 512; k += 64) {
        int kt = k >> 3, k8 = k & 7;
        int mt = b >> 4, gid = b & 7, r = (b >> 3) & 1;
        int tigp = k8 & 3, v = 2 * (k8 >> 2) + r;
        hs[k] = g_h2f[(TT - 1) & 1][kt * 512 + mt * 128 + (gid * 4 + tigp) * 4 + v];
    }
    __syncthreads();
    int o = threadIdx.x;
    float acc = bout[o];
    const float* wr = Wout + o * HH;
#pragma unroll 8
    for (int k = 0; k < HH; k++) acc = fmaf(hs[k], wr[k], acc);
    out[b * 64 + o] = acc;
}

// ---------------- launch ----------------
extern "C" void kernel_launch(void* const* d_in, const int* in_sizes, int n_in,
                              void* d_out, int out_size) {
    const float* x    = (const float*)d_in[0];
    const float* Wih0 = (const float*)d_in[1];
    const float* Whh0 = (const float*)d_in[2];
    const float* bih0 = (const float*)d_in[3];
    const float* bhh0 = (const float*)d_in[4];
    const float* Wih1 = (const float*)d_in[5];
    const float* Whh1 = (const float*)d_in[6];
    const float* bih1 = (const float*)d_in[7];
    const float* bhh1 = (const float*)d_in[8];
    const float* Wout = (const float*)d_in[9];
    const float* bout = (const float*)d_in[10];
    float* out = (float*)d_out;

    cudaFuncSetAttribute(lstm_kernel, cudaFuncAttributeMaxDynamicSharedMemorySize, SMEM_BYTES);

    reset_kernel<<<128, 256>>>();
    pack_kernel<<<128, 256>>>(Whh0, Wih1, Whh1, bih1, bhh1);
    xg0_kernel<<<TT * 64, 256>>>(x, Wih0, bih0, bhh0);
    lstm_kernel<<<GRID, NT, SMEM_BYTES>>>();
    out_kernel<<<64, 64>>>(Wout, bout, out);
}

// round 4
// speedup vs baseline: 3.7472x; 1.1276x over previous
#include <cuda_runtime.h>
#include <cstdint>

#define BB 64
#define TT 1500
#define FF 36
#define HH 512
#define NT 256          // threads per lstm CTA (8 warps: 2 k-split groups x 4 mt warps)
#define GRID 128

// ---------------- device globals ----------------
__device__ float g_xg0p[(size_t)TT * 64 * 128 * 16];  // 786MB: per-consumer-thread acc-init [t][c][tau][nt*4+p]
__device__ float g_wf1[64 * 16384];                   // layer1 B-fragments [c][kt64][p2][lane32][4]
__device__ float g_wf2[64 * 32768];                   // layer2 B-fragments [c][kt128][p2][lane32][4]
__device__ float g_b2p[64 * 128 * 8];                 // layer2 bias per consumer thread
__device__ float g_h1f[4][32768];                     // h1 ring, fragment layout [buf][kt64][mt4][lane32][4]
__device__ float g_h2f[2][32768];                     // h2 ring
__device__ unsigned g_f1[TT + 2];
__device__ unsigned g_f2[TT + 2];

// ---------------- helpers ----------------
__device__ __forceinline__ float tf32r(float x) {
    uint32_t u;
    asm("cvt.rna.tf32.f32 %0, %1;" : "=r"(u) : "f"(x));
    return __uint_as_float(u);
}
__device__ __forceinline__ float tanha(float x) {
    float y;
    asm("tanh.approx.f32 %0, %1;" : "=f"(y) : "f"(x));
    return y;
}
__device__ __forceinline__ float sigm(float x) { return fmaf(tanha(0.5f * x), 0.5f, 0.5f); }

__device__ __forceinline__ void mma8(float* d, float4 a, float b0, float b1) {
    asm volatile(
        "mma.sync.aligned.m16n8k8.row.col.f32.tf32.tf32.f32 "
        "{%0,%1,%2,%3},{%4,%5,%6,%7},{%8,%9},{%0,%1,%2,%3};\n"
        : "+f"(d[0]), "+f"(d[1]), "+f"(d[2]), "+f"(d[3])
        : "r"(__float_as_uint(a.x)), "r"(__float_as_uint(a.y)),
          "r"(__float_as_uint(a.z)), "r"(__float_as_uint(a.w)),
          "r"(__float_as_uint(b0)), "r"(__float_as_uint(b1)));
}

__device__ __forceinline__ void waitflag(const unsigned* p, unsigned tgt) {
    unsigned v;
    do {
        asm volatile("ld.acquire.gpu.global.u32 %0, [%1];" : "=r"(v) : "l"(p) : "memory");
    } while (v < tgt);
}
__device__ __forceinline__ void waitflag2(const unsigned* p, unsigned tp,
                                          const unsigned* q, unsigned tq) {
    unsigned v, w;
    do {
        asm volatile("ld.acquire.gpu.global.u32 %0, [%1];" : "=r"(v) : "l"(p) : "memory");
        asm volatile("ld.acquire.gpu.global.u32 %0, [%1];" : "=r"(w) : "l"(q) : "memory");
    } while (v < tp || w < tq);
}

// 32 k-tiles (half of a 512-K GEMM): A fragments direct from gmem, B fragments from smem
__device__ __forceinline__ void gemm32(float acc[4][4], const float4* __restrict__ Ap,
                                       const float4* __restrict__ Bp, int lane) {
    float4 aq[8];
#pragma unroll
    for (int i = 0; i < 8; i++) aq[i] = __ldcg(Ap + i * 128);
#pragma unroll 8
    for (int kt = 0; kt < 32; kt++) {
        float4 av = aq[kt & 7];
        float4 b0 = Bp[kt * 64 + lane];
        float4 b1 = Bp[kt * 64 + 32 + lane];
        if (kt < 24) aq[kt & 7] = __ldcg(Ap + (kt + 8) * 128);
        mma8(acc[0], av, b0.x, b0.y);
        mma8(acc[1], av, b0.z, b0.w);
        mma8(acc[2], av, b1.x, b1.y);
        mma8(acc[3], av, b1.z, b1.w);
    }
}

// ---------------- setup kernels ----------------
__global__ void reset_kernel() {
    int idx = blockIdx.x * 256 + threadIdx.x;
    if (idx < TT + 2) {
        g_f1[idx] = (idx == 0) ? 64u : 0u;
        g_f2[idx] = (idx == 0) ? 64u : 0u;
    }
    if (idx < 32768) {
        g_h1f[3][idx] = 0.f;  // h1[-1] buffer ((-1)&3 = 3)
        g_h2f[1][idx] = 0.f;  // h2[-1] buffer ((-1)&1 = 1)
    }
}

__global__ void pack_kernel(const float* __restrict__ Whh0, const float* __restrict__ Wih1,
                            const float* __restrict__ Whh1, const float* __restrict__ bih1,
                            const float* __restrict__ bhh1) {
    int cb = blockIdx.x;
    if (cb < 64) {
        int c = cb;
        float* dst = g_wf1 + c * 16384;
        for (int idx = threadIdx.x; idx < 16384; idx += 256) {
            int e = idx & 3, lane = (idx >> 2) & 31, p = (idx >> 7) & 1, kt = idx >> 8;
            int gid = lane >> 2, tig = lane & 3;
            int nt = p * 2 + (e >> 1);
            int k = kt * 8 + tig + 4 * (e & 1);
            int row = nt * HH + c * 8 + gid;
            dst[idx] = tf32r(Whh0[row * HH + k]);
        }
    } else {
        int c = cb - 64;
        float* dst = g_wf2 + c * 32768;
        for (int idx = threadIdx.x; idx < 32768; idx += 256) {
            int e = idx & 3, lane = (idx >> 2) & 31, p = (idx >> 7) & 1, kt = idx >> 8;
            int gid = lane >> 2, tig = lane & 3;
            int nt = p * 2 + (e >> 1);
            int ks = tig + 4 * (e & 1);
            int row = nt * HH + c * 8 + gid;
            float v = (kt < 64) ? Wih1[row * HH + kt * 8 + ks]
                                : Whh1[row * HH + (kt - 64) * 8 + ks];
            dst[idx] = tf32r(v);
        }
        for (int idx = threadIdx.x; idx < 128 * 8; idx += 256) {
            int tau = idx >> 3, q = idx & 7;
            int nt = q >> 1, jj = q & 1;
            int tig = tau & 3;
            int row = nt * HH + c * 8 + tig * 2 + jj;
            g_b2p[(c * 128 + tau) * 8 + q] = bih1[row] + bhh1[row];
        }
    }
}

// acc-init values for layer1: dot(x[b,t,:], W_ih0[row,:]) + b_ih0 + b_hh0, consumer-thread layout
__global__ void xg0_kernel(const float* __restrict__ x, const float* __restrict__ Wih0,
                           const float* __restrict__ bih0, const float* __restrict__ bhh0) {
    __shared__ float xs[64][37];
    __shared__ float ws[32][37];
    __shared__ float bsm[32];
    int t = blockIdx.x >> 6, c = blockIdx.x & 63;
    for (int i = threadIdx.x; i < 64 * FF; i += 256) {
        int b = i / FF, f = i - b * FF;
        xs[b][f] = x[((size_t)b * TT + t) * FF + f];
    }
    for (int i = threadIdx.x; i < 32 * FF; i += 256) {
        int r = i / FF, f = i - r * FF;
        int row = (r >> 3) * HH + c * 8 + (r & 7);
        ws[r][f] = Wih0[row * FF + f];
    }
    if (threadIdx.x < 32) {
        int r = threadIdx.x;
        int row = (r >> 3) * HH + c * 8 + (r & 7);
        bsm[r] = bih0[row] + bhh0[row];
    }
    __syncthreads();
    int tau = threadIdx.x & 127, half = threadIdx.x >> 7;
    int mt = tau >> 5, lane = tau & 31, gid = lane >> 2, tig = lane & 3;
    float* outp = g_xg0p + (((size_t)t * 64 + c) * 128 + tau) * 16 + half * 8;
#pragma unroll
    for (int q = 0; q < 2; q++) {
        int nt = half * 2 + q;
#pragma unroll
        for (int p = 0; p < 4; p++) {
            int b = mt * 16 + gid + 8 * (p >> 1);
            int hl = tig * 2 + (p & 1);
            int r = nt * 8 + hl;
            float acc = bsm[r];
#pragma unroll
            for (int f = 0; f < FF; f++) acc = fmaf(xs[b][f], ws[r][f], acc);
            outp[q * 4 + p] = acc;
        }
    }
}

// ---------------- persistent 2-layer LSTM ----------------
// smem: weights up to 8192 float4 (128KB) + Rsm 128*20 floats (10KB)
#define SMEM_BYTES (131072 + 10240)

__global__ void __launch_bounds__(NT, 1) lstm_kernel() {
    extern __shared__ float4 Bs4[];
    float* Rsm = (float*)(Bs4 + 8192);     // [128][20] partial-acc handoff

    const int cta = blockIdx.x;
    const int layer = cta >> 6;
    const int c = cta & 63;
    const int tid = threadIdx.x;
    const int ks = tid >> 7;               // k-split group (0 or 1)
    const int tl = tid & 127;              // role within group
    const int mt = tl >> 5, lane = tl & 31;
    const int tig = lane & 3;
    const int gid = lane >> 2;

    {   // weights -> smem (linear copy, already fragment-packed)
        const float4* wsrc = (const float4*)(layer ? (g_wf2 + c * 32768) : (g_wf1 + c * 16384));
        int tot = layer ? 8192 : 4096;
        for (int i = tid; i < tot; i += NT) Bs4[i] = wsrc[i];
    }
    float bias[16];
    if (layer && ks == 0) {
        const float* bp = g_b2p + (c * 128 + tl) * 8;
#pragma unroll
        for (int nt = 0; nt < 4; nt++) {
            float2 v = *(const float2*)(bp + nt * 2);
            bias[nt * 4 + 0] = v.x; bias[nt * 4 + 1] = v.y;
            bias[nt * 4 + 2] = v.x; bias[nt * 4 + 3] = v.y;
        }
    }
    float cst[4] = {0.f, 0.f, 0.f, 0.f};
    __syncthreads();

    const int kofsA = ks * 32 * 128;       // A float4 offset for this k-half
    const int kofsB = ks * 32 * 64;        // B float4 offset for this k-half

    for (int t = 0; t < TT; t++) {
        float acc[4][4];
        if (!layer) {
            float4 xg[4];
            if (ks == 0) {   // prefetch acc-init (DRAM) before the spin
                const float4* xp = (const float4*)(g_xg0p + (((size_t)t * 64 + c) * 128 + tl) * 16);
#pragma unroll
                for (int nt = 0; nt < 4; nt++) xg[nt] = __ldcg(xp + nt);
            }
            if (t >= 4) waitflag2(g_f2 + (t - 3), 64, g_f1 + t, 64);
            else        waitflag(g_f1 + t, 64);
            if (ks == 0) {
#pragma unroll
                for (int nt = 0; nt < 4; nt++) {
                    acc[nt][0] = xg[nt].x; acc[nt][1] = xg[nt].y;
                    acc[nt][2] = xg[nt].z; acc[nt][3] = xg[nt].w;
                }
            } else {
#pragma unroll
                for (int q = 0; q < 16; q++) acc[q >> 2][q & 3] = 0.f;
            }
            const float4* Ap = (const float4*)g_h1f + ((t - 1) & 3) * 8192 + kofsA + mt * 32 + lane;
            gemm32(acc, Ap, Bs4 + kofsB, lane);
        } else {
            if (ks == 0) {
#pragma unroll
                for (int q = 0; q < 16; q++) acc[q >> 2][q & 3] = bias[q];
            } else {
#pragma unroll
                for (int q = 0; q < 16; q++) acc[q >> 2][q & 3] = 0.f;
            }
            waitflag(g_f2 + t, 64);        // h2[t-1] ready
            const float4* Ap2 = (const float4*)g_h2f + ((t - 1) & 1) * 8192 + kofsA + mt * 32 + lane;
            gemm32(acc, Ap2, Bs4 + 64 * 64 + kofsB, lane);   // W_hh1 half (overlaps layer1 step t)
            waitflag(g_f1 + t + 1, 64);    // h1[t] ready
            const float4* Ap1 = (const float4*)g_h1f + (t & 3) * 8192 + kofsA + mt * 32 + lane;
            gemm32(acc, Ap1, Bs4 + kofsB, lane);             // W_ih1 half
        }
        // k-split reduction: upper group hands partials to lower group via smem
        if (ks == 1) {
            float4* rp = (float4*)(Rsm + tl * 20);
#pragma unroll
            for (int nt = 0; nt < 4; nt++)
                rp[nt] = make_float4(acc[nt][0], acc[nt][1], acc[nt][2], acc[nt][3]);
        }
        __syncthreads();
        if (ks == 0) {
            const float4* rp = (const float4*)(Rsm + tl * 20);
#pragma unroll
            for (int nt = 0; nt < 4; nt++) {
                float4 v = rp[nt];
                acc[nt][0] += v.x; acc[nt][1] += v.y;
                acc[nt][2] += v.z; acc[nt][3] += v.w;
            }
            // elementwise entirely in registers; write h in consumer fragment layout
            float* slab = (layer ? (float*)g_h2f + (t & 1) * 32768
                                 : (float*)g_h1f + (t & 3) * 32768) + c * 512 + mt * 128;
#pragma unroll
            for (int p = 0; p < 4; p++) {
                float ig = sigm(acc[0][p]);
                float fg = sigm(acc[1][p]);
                float gg = tanha(acc[2][p]);
                float og = sigm(acc[3][p]);
                float cv = fmaf(fg, cst[p], ig * gg);
                cst[p] = cv;
                float hv = og * tanha(cv);
                int hl = tig * 2 + (p & 1);
                int tigp = hl & 3;
                int v = 2 * (hl >> 2) + (p >> 1);
                slab[(gid * 4 + tigp) * 4 + v] = tf32r(hv);
            }
        }
        __syncthreads();
        if (tid == 0) {
            unsigned* fp = (layer ? g_f2 : g_f1) + t + 1;
            asm volatile("red.release.gpu.global.add.u32 [%0], 1;" ::"l"(fp) : "memory");
        }
    }
}

// ---------------- final projection ----------------
__global__ void out_kernel(const float* __restrict__ Wout, const float* __restrict__ bout,
                           float* __restrict__ out) {
    __shared__ float hs[512];
    int b = blockIdx.x;
    for (int k = threadIdx.x; k < 512; k += 64) {
        int kt = k >> 3, k8 = k & 7;
        int mt = b >> 4, gid = b & 7, r = (b >> 3) & 1;
        int tigp = k8 & 3, v = 2 * (k8 >> 2) + r;
        hs[k] = g_h2f[(TT - 1) & 1][kt * 512 + mt * 128 + (gid * 4 + tigp) * 4 + v];
    }
    __syncthreads();
    int o = threadIdx.x;
    float acc = bout[o];
    const float* wr = Wout + o * HH;
#pragma unroll 8
    for (int k = 0; k < HH; k++) acc = fmaf(hs[k], wr[k], acc);
    out[b * 64 + o] = acc;
}

// ---------------- launch ----------------
extern "C" void kernel_launch(void* const* d_in, const int* in_sizes, int n_in,
                              void* d_out, int out_size) {
    const float* x    = (const float*)d_in[0];
    const float* Wih0 = (const float*)d_in[1];
    const float* Whh0 = (const float*)d_in[2];
    const float* bih0 = (const float*)d_in[3];
    const float* bhh0 = (const float*)d_in[4];
    const float* Wih1 = (const float*)d_in[5];
    const float* Whh1 = (const float*)d_in[6];
    const float* bih1 = (const float*)d_in[7];
    const float* bhh1 = (const float*)d_in[8];
    const float* Wout = (const float*)d_in[9];
    const float* bout = (const float*)d_in[10];
    float* out = (float*)d_out;

    cudaFuncSetAttribute(lstm_kernel, cudaFuncAttributeMaxDynamicSharedMemorySize, SMEM_BYTES);

    reset_kernel<<<128, 256>>>();
    pack_kernel<<<128, 256>>>(Whh0, Wih1, Whh1, bih1, bhh1);
    xg0_kernel<<<TT * 64, 256>>>(x, Wih0, bih0, bhh0);
    lstm_kernel<<<GRID, NT, SMEM_BYTES>>>();
    out_kernel<<<64, 64>>>(Wout, bout, out);
}

// round 6
// speedup vs baseline: 3.9676x; 1.0588x over previous
#include <cuda_runtime.h>
#include <cuda_fp16.h>
#include <cstdint>

#define BB 64
#define TT 1500
#define FF 36
#define HH 512
#define NT 512          // 16 warps: ks2 x ns2 x mt4
#define GRID 64

// ---------------- device globals ----------------
__device__ float g_xg0p[(size_t)TT * 131072];   // 786MB acc-init [t][c32][ks][ns][mt][lane][8]
__device__ float g_b2p[32 * 4096];              // layer2 bias, per-thread layout [c][ks(dc)][ns][mt(dc)][lane][8]
__device__ uint32_t g_wf1[32 * 16384];          // layer1 B-frags fp16x2 [c][kt32][ns][h][lane][e]
__device__ uint32_t g_wf2[32 * 32768];          // layer2 B-frags [c][kt64][ns][h][lane][e]
__device__ uint32_t g_h1s[4 * 16384];           // h1 ring, fp16 A-fragment layout (64KB/slab)
__device__ uint32_t g_h2s[2 * 16384];           // h2 ring
struct alignas(128) Flag { unsigned v; unsigned pad[31]; };
__device__ Flag g_f1[TT + 2];
__device__ Flag g_f2[TT + 2];

// ---------------- helpers ----------------
__device__ __forceinline__ float tanha(float x) {
    float y;
    asm("tanh.approx.f32 %0, %1;" : "=f"(y) : "f"(x));
    return y;
}
__device__ __forceinline__ float sigm(float x) { return fmaf(tanha(0.5f * x), 0.5f, 0.5f); }

__device__ __forceinline__ uint32_t f2h2(float lo, float hi) {
    __half2 h = __floats2half2_rn(lo, hi);
    return *reinterpret_cast<uint32_t*>(&h);
}

__device__ __forceinline__ void mma16(float* d, uint4 a, uint32_t b0, uint32_t b1) {
    asm volatile(
        "mma.sync.aligned.m16n8k16.row.col.f32.f16.f16.f32 "
        "{%0,%1,%2,%3},{%4,%5,%6,%7},{%8,%9},{%0,%1,%2,%3};\n"
        : "+f"(d[0]), "+f"(d[1]), "+f"(d[2]), "+f"(d[3])
        : "r"(a.x), "r"(a.y), "r"(a.z), "r"(a.w), "r"(b0), "r"(b1));
}

__device__ __forceinline__ void waitflag(const unsigned* p, unsigned tgt) {
    unsigned v;
    do {
        asm volatile("ld.acquire.gpu.global.u32 %0, [%1];" : "=r"(v) : "l"(p) : "memory");
    } while (v < tgt);
}
__device__ __forceinline__ void waitflag2(const unsigned* p, unsigned tp,
                                          const unsigned* q, unsigned tq) {
    unsigned v, w;
    do {
        asm volatile("ld.acquire.gpu.global.u32 %0, [%1];" : "=r"(v) : "l"(p) : "memory");
        asm volatile("ld.acquire.gpu.global.u32 %0, [%1];" : "=r"(w) : "l"(q) : "memory");
    } while (v < tp || w < tq);
}

// 16 k16-tiles (K=256): A uint4 frags from gmem, B from smem. Per kt: 1 LDG.128 + 2 LDS.128 + 4 MMA.
__device__ __forceinline__ void gemm16(float acc[4][4], const uint4* __restrict__ Ap,
                                       const uint4* __restrict__ Bp) {
    uint4 aq[8];
#pragma unroll
    for (int i = 0; i < 8; i++) aq[i] = __ldcg(Ap + i * 128);
#pragma unroll
    for (int i = 0; i < 16; i++) {
        uint4 av = aq[i & 7];
        uint4 q1 = Bp[i * 128];
        uint4 q2 = Bp[i * 128 + 32];
        if (i < 8) aq[i & 7] = __ldcg(Ap + (i + 8) * 128);
        mma16(acc[0], av, q1.x, q2.x);
        mma16(acc[1], av, q1.y, q2.y);
        mma16(acc[2], av, q1.z, q2.z);
        mma16(acc[3], av, q1.w, q2.w);
    }
}

// ---------------- setup kernels ----------------
__global__ void reset_kernel() {
    int idx = blockIdx.x * 256 + threadIdx.x;
    if (idx < TT + 2) {
        g_f1[idx].v = (idx == 0) ? 32u : 0u;
        g_f2[idx].v = (idx == 0) ? 32u : 0u;
    }
    if (idx < 16384) {
        g_h1s[3 * 16384 + idx] = 0u;   // h1[-1] slab ((-1)&3 = 3)
        g_h2s[16384 + idx] = 0u;       // h2[-1] slab ((-1)&1 = 1)
    }
}

__global__ void pack_kernel(const float* __restrict__ Whh0, const float* __restrict__ Wih1,
                            const float* __restrict__ Whh1, const float* __restrict__ bih1,
                            const float* __restrict__ bhh1) {
    int cb = blockIdx.x;
    if (cb < 32) {
        int c = cb;
        uint32_t* dst = g_wf1 + c * 16384;
        for (int idx = threadIdx.x; idx < 16384; idx += 256) {
            int e = idx & 3, lane = (idx >> 2) & 31, h = (idx >> 7) & 1;
            int ns = (idx >> 8) & 1, kt = idx >> 9;
            int gid = lane >> 2, tig = lane & 3;
            int r = e * 512 + c * 16 + ns * 8 + gid;
            int k = kt * 16 + h * 8 + tig * 2;
            dst[idx] = f2h2(Whh0[r * HH + k], Whh0[r * HH + k + 1]);
        }
    } else {
        int c = cb - 32;
        uint32_t* dst = g_wf2 + c * 32768;
        for (int idx = threadIdx.x; idx < 32768; idx += 256) {
            int e = idx & 3, lane = (idx >> 2) & 31, h = (idx >> 7) & 1;
            int ns = (idx >> 8) & 1, kt = idx >> 9;
            int gid = lane >> 2, tig = lane & 3;
            int r = e * 512 + c * 16 + ns * 8 + gid;
            float v0, v1;
            if (kt < 32) {
                int k = kt * 16 + h * 8 + tig * 2;
                v0 = Wih1[r * HH + k]; v1 = Wih1[r * HH + k + 1];
            } else {
                int k = (kt - 32) * 16 + h * 8 + tig * 2;
                v0 = Whh1[r * HH + k]; v1 = Whh1[r * HH + k + 1];
            }
            dst[idx] = f2h2(v0, v1);
        }
        // bias layout EXACTLY matches consumer thrOff = c*4096 + ks*2048 + ns*1024 + mt*256 + lane*8 + j
        // (value independent of the don't-care ks bit 11 and mt bits 8..9)
        for (int idx = threadIdx.x; idx < 4096; idx += 256) {
            int j = idx & 7, lane = (idx >> 3) & 31, ns = (idx >> 10) & 1;
            int r = (j >> 1) * 512 + c * 16 + ns * 8 + (lane & 3) * 2 + (j & 1);
            g_b2p[c * 4096 + idx] = bih1[r] + bhh1[r];
        }
    }
}

// acc-init for layer1: dot(x[b,t,:], W_ih0[r,:]) + b_ih0[r] + b_hh0[r]
__global__ void xg0_kernel(const float* __restrict__ x, const float* __restrict__ Wih0,
                           const float* __restrict__ bih0, const float* __restrict__ bhh0) {
    __shared__ float xs[64][37];
    __shared__ float ws[64][37];
    __shared__ float bsm[64];
    int t = blockIdx.x >> 5, c = blockIdx.x & 31;
    for (int i = threadIdx.x; i < 64 * FF; i += 256) {
        int b = i / FF, f = i - b * FF;
        xs[b][f] = x[((size_t)b * TT + t) * FF + f];
    }
    for (int i = threadIdx.x; i < 64 * FF; i += 256) {
        int rl = i / FF, f = i - rl * FF;
        int r = (rl >> 4) * 512 + c * 16 + (rl & 15);
        ws[rl][f] = Wih0[r * FF + f];
    }
    if (threadIdx.x < 64) {
        int rl = threadIdx.x;
        int r = (rl >> 4) * 512 + c * 16 + (rl & 15);
        bsm[rl] = bih0[r] + bhh0[r];
    }
    __syncthreads();
    int ks = threadIdx.x >> 7, ns = (threadIdx.x >> 6) & 1;
    int sub = threadIdx.x & 63, m2 = sub >> 5, lane = sub & 31;
    int gid = lane >> 2, tig = lane & 3;
#pragma unroll
    for (int mh = 0; mh < 2; mh++) {
        int mt = m2 + 2 * mh;
        int b = mt * 16 + gid + 8 * ks;
        float v[8];
#pragma unroll
        for (int j = 0; j < 8; j++) {
            int rl = (j >> 1) * 16 + ns * 8 + tig * 2 + (j & 1);
            float acc = bsm[rl];
#pragma unroll
            for (int f = 0; f < FF; f++) acc = fmaf(xs[b][f], ws[rl][f], acc);
            v[j] = acc;
        }
        size_t off = (size_t)t * 131072 + c * 4096 + ks * 2048 + ns * 1024 + mt * 256 + (size_t)lane * 8;
        float4* op = (float4*)(g_xg0p + off);
        op[0] = make_float4(v[0], v[1], v[2], v[3]);
        op[1] = make_float4(v[4], v[5], v[6], v[7]);
    }
}

// ---------------- persistent 2-layer LSTM ----------------
// smem: Bs4 uint4[8192] (128KB weights) + RA/RB float4[1024] (16KB exchange)
#define SMEM_BYTES 147456

__global__ void __launch_bounds__(NT, 1) lstm_kernel() {
    extern __shared__ uint4 smemu[];
    uint4* Bs4 = smemu;
    float4* RA = (float4*)(smemu + 8192);
    float4* RB = RA + 512;

    const int cta = blockIdx.x;
    const int layer = cta >> 5;
    const int c = cta & 31;
    const int tid = threadIdx.x;
    const int ks = tid >> 8;
    const int ns = (tid >> 7) & 1;
    const int mt = (tid >> 5) & 3;
    const int lane = tid & 31;
    const int idx = (ns * 4 + mt) * 32 + lane;
    const size_t thrOff = c * 4096 + ks * 2048 + ns * 1024 + mt * 256 + (size_t)lane * 8;

    {   // weights -> smem (fragment-packed already)
        const uint4* wsrc = (const uint4*)(layer ? (g_wf2 + c * 32768) : (g_wf1 + c * 16384));
        int tot = layer ? 8192 : 4096;
        for (int i = tid; i < tot; i += NT) Bs4[i] = wsrc[i];
    }
    float cst0 = 0.f, cst1 = 0.f;
    __syncthreads();

    for (int t = 0; t < TT; t++) {
        float acc[4][4];
#pragma unroll
        for (int q = 0; q < 16; q++) acc[q >> 2][q & 3] = 0.f;
        float4 f4a, f4b;
        if (!layer) {
            const float4* xp = (const float4*)(g_xg0p + (size_t)t * 131072 + thrOff);
            f4a = __ldcg(xp); f4b = __ldcg(xp + 1);
            if (t >= 4) waitflag2(&g_f2[t - 3].v, 32, &g_f1[t].v, 32);
            else        waitflag(&g_f1[t].v, 32);
        } else {
            const float4* bp = (const float4*)(g_b2p + thrOff);
            f4a = bp[0]; f4b = bp[1];
            waitflag(&g_f2[t].v, 32);
        }
        if (ks == 0) {
            acc[0][0] = f4a.x; acc[0][1] = f4a.y; acc[1][0] = f4a.z; acc[1][1] = f4a.w;
            acc[2][0] = f4b.x; acc[2][1] = f4b.y; acc[3][0] = f4b.z; acc[3][1] = f4b.w;
        } else {
            acc[0][2] = f4a.x; acc[0][3] = f4a.y; acc[1][2] = f4a.z; acc[1][3] = f4a.w;
            acc[2][2] = f4b.x; acc[2][3] = f4b.y; acc[3][2] = f4b.z; acc[3][3] = f4b.w;
        }
        if (!layer) {
            const uint4* Ap = (const uint4*)(g_h1s + ((t - 1) & 3) * 16384) + ks * 2048 + mt * 32 + lane;
            gemm16(acc, Ap, Bs4 + ks * 2048 + ns * 64 + lane);
        } else {
            const uint4* Ap2 = (const uint4*)(g_h2s + ((t - 1) & 1) * 16384) + ks * 2048 + mt * 32 + lane;
            gemm16(acc, Ap2, Bs4 + (32 + ks * 16) * 128 + ns * 64 + lane);   // W_hh1 half
            waitflag(&g_f1[t + 1].v, 32);                                     // h1[t] ready
            const uint4* Ap1 = (const uint4*)(g_h1s + (t & 3) * 16384) + ks * 2048 + mt * 32 + lane;
            gemm16(acc, Ap1, Bs4 + ks * 2048 + ns * 64 + lane);               // W_ih1 half
        }
        // k-split exchange (each group ships the p-half it doesn't own)
        float4 wa, wb;
        if (ks == 0) {
            wa = make_float4(acc[0][2], acc[0][3], acc[1][2], acc[1][3]);
            wb = make_float4(acc[2][2], acc[2][3], acc[3][2], acc[3][3]);
        } else {
            wa = make_float4(acc[0][0], acc[0][1], acc[1][0], acc[1][1]);
            wb = make_float4(acc[2][0], acc[2][1], acc[3][0], acc[3][1]);
        }
        RA[(ks ^ 1) * 256 + idx] = wa;
        RB[(ks ^ 1) * 256 + idx] = wb;
        __syncthreads();
        float4 fa = RA[ks * 256 + idx];
        float4 fb = RB[ks * 256 + idx];
        float gi0, gi1, gf0, gf1, gg0, gg1, go0, go1;
        if (ks == 0) {
            gi0 = acc[0][0] + fa.x; gi1 = acc[0][1] + fa.y;
            gf0 = acc[1][0] + fa.z; gf1 = acc[1][1] + fa.w;
            gg0 = acc[2][0] + fb.x; gg1 = acc[2][1] + fb.y;
            go0 = acc[3][0] + fb.z; go1 = acc[3][1] + fb.w;
        } else {
            gi0 = acc[0][2] + fa.x; gi1 = acc[0][3] + fa.y;
            gf0 = acc[1][2] + fa.z; gf1 = acc[1][3] + fa.w;
            gg0 = acc[2][2] + fb.x; gg1 = acc[2][3] + fb.y;
            go0 = acc[3][2] + fb.z; go1 = acc[3][3] + fb.w;
        }
        float cv0 = fmaf(sigm(gf0), cst0, sigm(gi0) * tanha(gg0));
        float cv1 = fmaf(sigm(gf1), cst1, sigm(gi1) * tanha(gg1));
        cst0 = cv0; cst1 = cv1;
        float h0 = sigm(go0) * tanha(cv0);
        float h1 = sigm(go1) * tanha(cv1);
        uint32_t hv = f2h2(h0, h1);
        uint32_t* slab = layer ? (g_h2s + (t & 1) * 16384) : (g_h1s + (t & 3) * 16384);
        slab[((c * 4 + mt) * 32 + lane) * 4 + ks + 2 * ns] = hv;
        __syncthreads();
        if (tid == 0) {
            unsigned* fp = layer ? &g_f2[t + 1].v : &g_f1[t + 1].v;
            asm volatile("red.release.gpu.global.add.u32 [%0], 1;" ::"l"(fp) : "memory");
        }
    }
}

// ---------------- final projection ----------------
__global__ void out_kernel(const float* __restrict__ Wout, const float* __restrict__ bout,
                           float* __restrict__ out) {
    __shared__ float hs[512];
    int b = blockIdx.x;
    int mt = b >> 4, ksb = (b >> 3) & 1, gid = b & 7;
    const uint32_t* slab = g_h2s + ((TT - 1) & 1) * 16384;
    for (int k = threadIdx.x; k < 512; k += 64) {
        int cc = k >> 4, ns = (k >> 3) & 1, tig = (k & 7) >> 1, par = k & 1;
        uint32_t v = slab[((cc * 4 + mt) * 32 + gid * 4 + tig) * 4 + ksb + 2 * ns];
        __half2 h2v = *reinterpret_cast<__half2*>(&v);
        hs[k] = par ? __high2float(h2v) : __low2float(h2v);
    }
    __syncthreads();
    int o = threadIdx.x;
    float acc = bout[o];
    const float* wr = Wout + o * HH;
#pragma unroll 8
    for (int k = 0; k < HH; k++) acc = fmaf(hs[k], wr[k], acc);
    out[b * 64 + o] = acc;
}

// ---------------- launch ----------------
extern "C" void kernel_launch(void* const* d_in, const int* in_sizes, int n_in,
                              void* d_out, int out_size) {
    const float* x    = (const float*)d_in[0];
    const float* Wih0 = (const float*)d_in[1];
    const float* Whh0 = (const float*)d_in[2];
    const float* bih0 = (const float*)d_in[3];
    const float* bhh0 = (const float*)d_in[4];
    const float* Wih1 = (const float*)d_in[5];
    const float* Whh1 = (const float*)d_in[6];
    const float* bih1 = (const float*)d_in[7];
    const float* bhh1 = (const float*)d_in[8];
    const float* Wout = (const float*)d_in[9];
    const float* bout = (const float*)d_in[10];
    float* out = (float*)d_out;

    cudaFuncSetAttribute(lstm_kernel, cudaFuncAttributeMaxDynamicSharedMemorySize, SMEM_BYTES);

    reset_kernel<<<64, 256>>>();
    pack_kernel<<<64, 256>>>(Whh0, Wih1, Whh1, bih1, bhh1);
    xg0_kernel<<<TT * 32, 256>>>(x, Wih0, bih0, bhh0);
    lstm_kernel<<<GRID, NT, SMEM_BYTES>>>();
    out_kernel<<<64, 64>>>(Wout, bout, out);
}

// round 7
// speedup vs baseline: 4.0307x; 1.0159x over previous
#include <cuda_runtime.h>
#include <cuda_fp16.h>
#include <cstdint>

#define BB 64
#define TT 1500
#define FF 36
#define HH 512
#define NT 512          // 16 warps: ks2 x ns2 x mt4
#define GRID 64

// ---------------- device globals ----------------
__device__ float g_xg0p[(size_t)TT * 131072];   // 786MB acc-init [t][c32][ks][ns][mt][lane][8]
__device__ float g_b2p[32 * 4096];              // layer2 bias, per-thread layout [c][ks(dc)][ns][mt(dc)][lane][8]
__device__ uint32_t g_wf1[32 * 16384];          // layer1 B-frags fp16x2 [c][kt32][ns][h][lane][e]
__device__ uint32_t g_wf2[32 * 32768];          // layer2 B-frags [c][kt64][ns][h][lane][e]
__device__ uint32_t g_h1s[4 * 16384];           // h1 ring, fp16 A-fragment layout (64KB/slab)
__device__ uint32_t g_h2s[2 * 16384];           // h2 ring
struct alignas(128) Flag { unsigned v; unsigned pad[31]; };
__device__ Flag g_f1[TT + 2];
__device__ Flag g_f2[TT + 2];

// ---------------- helpers ----------------
__device__ __forceinline__ float tanha(float x) {
    float y;
    asm("tanh.approx.f32 %0, %1;" : "=f"(y) : "f"(x));
    return y;
}
__device__ __forceinline__ float sigm(float x) { return fmaf(tanha(0.5f * x), 0.5f, 0.5f); }

__device__ __forceinline__ uint32_t f2h2(float lo, float hi) {
    __half2 h = __floats2half2_rn(lo, hi);
    return *reinterpret_cast<uint32_t*>(&h);
}

__device__ __forceinline__ void mma16(float* d, uint4 a, uint32_t b0, uint32_t b1) {
    asm volatile(
        "mma.sync.aligned.m16n8k16.row.col.f32.f16.f16.f32 "
        "{%0,%1,%2,%3},{%4,%5,%6,%7},{%8,%9},{%0,%1,%2,%3};\n"
        : "+f"(d[0]), "+f"(d[1]), "+f"(d[2]), "+f"(d[3])
        : "r"(a.x), "r"(a.y), "r"(a.z), "r"(a.w), "r"(b0), "r"(b1));
}

__device__ __forceinline__ void waitflag(const unsigned* p, unsigned tgt) {
    unsigned v;
    do {
        asm volatile("ld.acquire.gpu.global.u32 %0, [%1];" : "=r"(v) : "l"(p) : "memory");
    } while (v < tgt);
}
__device__ __forceinline__ void waitflag2(const unsigned* p, unsigned tp,
                                          const unsigned* q, unsigned tq) {
    unsigned v, w;
    do {
        asm volatile("ld.acquire.gpu.global.u32 %0, [%1];" : "=r"(v) : "l"(p) : "memory");
        asm volatile("ld.acquire.gpu.global.u32 %0, [%1];" : "=r"(w) : "l"(q) : "memory");
    } while (v < tp || w < tq);
}

// CTA-wide wait: ONLY tid 0 spins on the L2 flag (kills the 32k-thread poll storm);
// everyone else parks on the barrier. acquire + bar.sync = the CG grid-sync idiom.
__device__ __forceinline__ void ctawait(const unsigned* p, unsigned tgt) {
    if (threadIdx.x == 0) waitflag(p, tgt);
    __syncthreads();
}
__device__ __forceinline__ void ctawait2(const unsigned* p, unsigned tp,
                                         const unsigned* q, unsigned tq) {
    if (threadIdx.x == 0) waitflag2(p, tp, q, tq);
    __syncthreads();
}

// 16 k16-tiles (K=256): A uint4 frags from gmem, B from smem. Per kt: 1 LDG.128 + 2 LDS.128 + 4 MMA.
__device__ __forceinline__ void gemm16(float acc[4][4], const uint4* __restrict__ Ap,
                                       const uint4* __restrict__ Bp) {
    uint4 aq[8];
#pragma unroll
    for (int i = 0; i < 8; i++) aq[i] = __ldcg(Ap + i * 128);
#pragma unroll
    for (int i = 0; i < 16; i++) {
        uint4 av = aq[i & 7];
        uint4 q1 = Bp[i * 128];
        uint4 q2 = Bp[i * 128 + 32];
        if (i < 8) aq[i & 7] = __ldcg(Ap + (i + 8) * 128);
        mma16(acc[0], av, q1.x, q2.x);
        mma16(acc[1], av, q1.y, q2.y);
        mma16(acc[2], av, q1.z, q2.z);
        mma16(acc[3], av, q1.w, q2.w);
    }
}

// ---------------- setup kernels ----------------
__global__ void reset_kernel() {
    int idx = blockIdx.x * 256 + threadIdx.x;
    if (idx < TT + 2) {
        g_f1[idx].v = (idx == 0) ? 32u : 0u;
        g_f2[idx].v = (idx == 0) ? 32u : 0u;
    }
    if (idx < 16384) {
        g_h1s[3 * 16384 + idx] = 0u;   // h1[-1] slab ((-1)&3 = 3)
        g_h2s[16384 + idx] = 0u;       // h2[-1] slab ((-1)&1 = 1)
    }
}

__global__ void pack_kernel(const float* __restrict__ Whh0, const float* __restrict__ Wih1,
                            const float* __restrict__ Whh1, const float* __restrict__ bih1,
                            const float* __restrict__ bhh1) {
    int cb = blockIdx.x;
    if (cb < 32) {
        int c = cb;
        uint32_t* dst = g_wf1 + c * 16384;
        for (int idx = threadIdx.x; idx < 16384; idx += 256) {
            int e = idx & 3, lane = (idx >> 2) & 31, h = (idx >> 7) & 1;
            int ns = (idx >> 8) & 1, kt = idx >> 9;
            int gid = lane >> 2, tig = lane & 3;
            int r = e * 512 + c * 16 + ns * 8 + gid;
            int k = kt * 16 + h * 8 + tig * 2;
            dst[idx] = f2h2(Whh0[r * HH + k], Whh0[r * HH + k + 1]);
        }
    } else {
        int c = cb - 32;
        uint32_t* dst = g_wf2 + c * 32768;
        for (int idx = threadIdx.x; idx < 32768; idx += 256) {
            int e = idx & 3, lane = (idx >> 2) & 31, h = (idx >> 7) & 1;
            int ns = (idx >> 8) & 1, kt = idx >> 9;
            int gid = lane >> 2, tig = lane & 3;
            int r = e * 512 + c * 16 + ns * 8 + gid;
            float v0, v1;
            if (kt < 32) {
                int k = kt * 16 + h * 8 + tig * 2;
                v0 = Wih1[r * HH + k]; v1 = Wih1[r * HH + k + 1];
            } else {
                int k = (kt - 32) * 16 + h * 8 + tig * 2;
                v0 = Whh1[r * HH + k]; v1 = Whh1[r * HH + k + 1];
            }
            dst[idx] = f2h2(v0, v1);
        }
        // bias layout EXACTLY matches consumer thrOff = c*4096 + ks*2048 + ns*1024 + mt*256 + lane*8 + j
        for (int idx = threadIdx.x; idx < 4096; idx += 256) {
            int j = idx & 7, lane = (idx >> 3) & 31, ns = (idx >> 10) & 1;
            int r = (j >> 1) * 512 + c * 16 + ns * 8 + (lane & 3) * 2 + (j & 1);
            g_b2p[c * 4096 + idx] = bih1[r] + bhh1[r];
        }
    }
}

// acc-init for layer1: dot(x[b,t,:], W_ih0[r,:]) + b_ih0[r] + b_hh0[r]
__global__ void xg0_kernel(const float* __restrict__ x, const float* __restrict__ Wih0,
                           const float* __restrict__ bih0, const float* __restrict__ bhh0) {
    __shared__ float xs[64][37];
    __shared__ float ws[64][37];
    __shared__ float bsm[64];
    int t = blockIdx.x >> 5, c = blockIdx.x & 31;
    for (int i = threadIdx.x; i < 64 * FF; i += 256) {
        int b = i / FF, f = i - b * FF;
        xs[b][f] = x[((size_t)b * TT + t) * FF + f];
    }
    for (int i = threadIdx.x; i < 64 * FF; i += 256) {
        int rl = i / FF, f = i - rl * FF;
        int r = (rl >> 4) * 512 + c * 16 + (rl & 15);
        ws[rl][f] = Wih0[r * FF + f];
    }
    if (threadIdx.x < 64) {
        int rl = threadIdx.x;
        int r = (rl >> 4) * 512 + c * 16 + (rl & 15);
        bsm[rl] = bih0[r] + bhh0[r];
    }
    __syncthreads();
    int ks = threadIdx.x >> 7, ns = (threadIdx.x >> 6) & 1;
    int sub = threadIdx.x & 63, m2 = sub >> 5, lane = sub & 31;
    int gid = lane >> 2, tig = lane & 3;
#pragma unroll
    for (int mh = 0; mh < 2; mh++) {
        int mt = m2 + 2 * mh;
        int b = mt * 16 + gid + 8 * ks;
        float v[8];
#pragma unroll
        for (int j = 0; j < 8; j++) {
            int rl = (j >> 1) * 16 + ns * 8 + tig * 2 + (j & 1);
            float acc = bsm[rl];
#pragma unroll
            for (int f = 0; f < FF; f++) acc = fmaf(xs[b][f], ws[rl][f], acc);
            v[j] = acc;
        }
        size_t off = (size_t)t * 131072 + c * 4096 + ks * 2048 + ns * 1024 + mt * 256 + (size_t)lane * 8;
        float4* op = (float4*)(g_xg0p + off);
        op[0] = make_float4(v[0], v[1], v[2], v[3]);
        op[1] = make_float4(v[4], v[5], v[6], v[7]);
    }
}

// ---------------- persistent 2-layer LSTM ----------------
// smem: Bs4 uint4[8192] (128KB weights) + RA/RB float4[1024] (16KB exchange)
#define SMEM_BYTES 147456

__global__ void __launch_bounds__(NT, 1) lstm_kernel() {
    extern __shared__ uint4 smemu[];
    uint4* Bs4 = smemu;
    float4* RA = (float4*)(smemu + 8192);
    float4* RB = RA + 512;

    const int cta = blockIdx.x;
    const int layer = cta >> 5;
    const int c = cta & 31;
    const int tid = threadIdx.x;
    const int ks = tid >> 8;
    const int ns = (tid >> 7) & 1;
    const int mt = (tid >> 5) & 3;
    const int lane = tid & 31;
    const int idx = (ns * 4 + mt) * 32 + lane;
    const size_t thrOff = c * 4096 + ks * 2048 + ns * 1024 + mt * 256 + (size_t)lane * 8;

    {   // weights -> smem (fragment-packed already)
        const uint4* wsrc = (const uint4*)(layer ? (g_wf2 + c * 32768) : (g_wf1 + c * 16384));
        int tot = layer ? 8192 : 4096;
        for (int i = tid; i < tot; i += NT) Bs4[i] = wsrc[i];
    }
    float cst0 = 0.f, cst1 = 0.f;
    __syncthreads();

    for (int t = 0; t < TT; t++) {
        float acc[4][4];
#pragma unroll
        for (int q = 0; q < 16; q++) acc[q >> 2][q & 3] = 0.f;
        float4 f4a, f4b;
        if (!layer) {
            const float4* xp = (const float4*)(g_xg0p + (size_t)t * 131072 + thrOff);
            f4a = __ldcg(xp); f4b = __ldcg(xp + 1);
            if (t >= 4) ctawait2(&g_f2[t - 3].v, 32, &g_f1[t].v, 32);
            else        ctawait(&g_f1[t].v, 32);
        } else {
            const float4* bp = (const float4*)(g_b2p + thrOff);
            f4a = bp[0]; f4b = bp[1];
            ctawait(&g_f2[t].v, 32);
        }
        if (ks == 0) {
            acc[0][0] = f4a.x; acc[0][1] = f4a.y; acc[1][0] = f4a.z; acc[1][1] = f4a.w;
            acc[2][0] = f4b.x; acc[2][1] = f4b.y; acc[3][0] = f4b.z; acc[3][1] = f4b.w;
        } else {
            acc[0][2] = f4a.x; acc[0][3] = f4a.y; acc[1][2] = f4a.z; acc[1][3] = f4a.w;
            acc[2][2] = f4b.x; acc[2][3] = f4b.y; acc[3][2] = f4b.z; acc[3][3] = f4b.w;
        }
        if (!layer) {
            const uint4* Ap = (const uint4*)(g_h1s + ((t - 1) & 3) * 16384) + ks * 2048 + mt * 32 + lane;
            gemm16(acc, Ap, Bs4 + ks * 2048 + ns * 64 + lane);
        } else {
            const uint4* Ap2 = (const uint4*)(g_h2s + ((t - 1) & 1) * 16384) + ks * 2048 + mt * 32 + lane;
            gemm16(acc, Ap2, Bs4 + (32 + ks * 16) * 128 + ns * 64 + lane);   // W_hh1 half
            ctawait(&g_f1[t + 1].v, 32);                                      // h1[t] ready
            const uint4* Ap1 = (const uint4*)(g_h1s + (t & 3) * 16384) + ks * 2048 + mt * 32 + lane;
            gemm16(acc, Ap1, Bs4 + ks * 2048 + ns * 64 + lane);               // W_ih1 half
        }
        // k-split exchange (each group ships the p-half it doesn't own)
        float4 wa, wb;
        if (ks == 0) {
            wa = make_float4(acc[0][2], acc[0][3], acc[1][2], acc[1][3]);
            wb = make_float4(acc[2][2], acc[2][3], acc[3][2], acc[3][3]);
        } else {
            wa = make_float4(acc[0][0], acc[0][1], acc[1][0], acc[1][1]);
            wb = make_float4(acc[2][0], acc[2][1], acc[3][0], acc[3][1]);
        }
        RA[(ks ^ 1) * 256 + idx] = wa;
        RB[(ks ^ 1) * 256 + idx] = wb;
        __syncthreads();
        float4 fa = RA[ks * 256 + idx];
        float4 fb = RB[ks * 256 + idx];
        float gi0, gi1, gf0, gf1, gg0, gg1, go0, go1;
        if (ks == 0) {
            gi0 = acc[0][0] + fa.x; gi1 = acc[0][1] + fa.y;
            gf0 = acc[1][0] + fa.z; gf1 = acc[1][1] + fa.w;
            gg0 = acc[2][0] + fb.x; gg1 = acc[2][1] + fb.y;
            go0 = acc[3][0] + fb.z; go1 = acc[3][1] + fb.w;
        } else {
            gi0 = acc[0][2] + fa.x; gi1 = acc[0][3] + fa.y;
            gf0 = acc[1][2] + fa.z; gf1 = acc[1][3] + fa.w;
            gg0 = acc[2][2] + fb.x; gg1 = acc[2][3] + fb.y;
            go0 = acc[3][2] + fb.z; go1 = acc[3][3] + fb.w;
        }
        float cv0 = fmaf(sigm(gf0), cst0, sigm(gi0) * tanha(gg0));
        float cv1 = fmaf(sigm(gf1), cst1, sigm(gi1) * tanha(gg1));
        cst0 = cv0; cst1 = cv1;
        float h0 = sigm(go0) * tanha(cv0);
        float h1 = sigm(go1) * tanha(cv1);
        uint32_t hv = f2h2(h0, h1);
        uint32_t* slab = layer ? (g_h2s + (t & 1) * 16384) : (g_h1s + (t & 3) * 16384);
        slab[((c * 4 + mt) * 32 + lane) * 4 + ks + 2 * ns] = hv;
        __syncthreads();
        if (tid == 0) {
            unsigned* fp = layer ? &g_f2[t + 1].v : &g_f1[t + 1].v;
            asm volatile("red.release.gpu.global.add.u32 [%0], 1;" ::"l"(fp) : "memory");
        }
    }
}

// ---------------- final projection ----------------
__global__ void out_kernel(const float* __restrict__ Wout, const float* __restrict__ bout,
                           float* __restrict__ out) {
    __shared__ float hs[512];
    int b = blockIdx.x;
    int mt = b >> 4, ksb = (b >> 3) & 1, gid = b & 7;
    const uint32_t* slab = g_h2s + ((TT - 1) & 1) * 16384;
    for (int k = threadIdx.x; k < 512; k += 64) {
        int cc = k >> 4, ns = (k >> 3) & 1, tig = (k & 7) >> 1, par = k & 1;
        uint32_t v = slab[((cc * 4 + mt) * 32 + gid * 4 + tig) * 4 + ksb + 2 * ns];
        __half2 h2v = *reinterpret_cast<__half2*>(&v);
        hs[k] = par ? __high2float(h2v) : __low2float(h2v);
    }
    __syncthreads();
    int o = threadIdx.x;
    float acc = bout[o];
    const float* wr = Wout + o * HH;
#pragma unroll 8
    for (int k = 0; k < HH; k++) acc = fmaf(hs[k], wr[k], acc);
    out[b * 64 + o] = acc;
}

// ---------------- launch ----------------
extern "C" void kernel_launch(void* const* d_in, const int* in_sizes, int n_in,
                              void* d_out, int out_size) {
    const float* x    = (const float*)d_in[0];
    const float* Wih0 = (const float*)d_in[1];
    const float* Whh0 = (const float*)d_in[2];
    const float* bih0 = (const float*)d_in[3];
    const float* bhh0 = (const float*)d_in[4];
    const float* Wih1 = (const float*)d_in[5];
    const float* Whh1 = (const float*)d_in[6];
    const float* bih1 = (const float*)d_in[7];
    const float* bhh1 = (const float*)d_in[8];
    const float* Wout = (const float*)d_in[9];
    const float* bout = (const float*)d_in[10];
    float* out = (float*)d_out;

    cudaFuncSetAttribute(lstm_kernel, cudaFuncAttributeMaxDynamicSharedMemorySize, SMEM_BYTES);

    reset_kernel<<<64, 256>>>();
    pack_kernel<<<64, 256>>>(Whh0, Wih1, Whh1, bih1, bhh1);
    xg0_kernel<<<TT * 32, 256>>>(x, Wih0, bih0, bhh0);
    lstm_kernel<<<GRID, NT, SMEM_BYTES>>>();
    out_kernel<<<64, 64>>>(Wout, bout, out);
}

// round 8
// speedup vs baseline: 4.3780x; 1.0862x over previous
#include <cuda_runtime.h>
#include <cuda_fp16.h>
#include <cstdint>

#define BB 64
#define TT 1500
#define FF 36
#define HH 512
#define NT 512          // 16 warps: ks2 x ns2 x mt4
#define GRID 64

// ---------------- device globals ----------------
__device__ float g_xg0p[(size_t)TT * 131072];   // 786MB acc-init [t][c32][ks][ns][mt][lane][8]
__device__ float g_b2p[32 * 4096];              // layer2 bias, per-thread layout
__device__ uint32_t g_wf1[32 * 16384];          // layer1 B-frags fp16x2
__device__ uint32_t g_wf2[32 * 32768];          // layer2 B-frags
__device__ uint32_t g_h1s[4 * 16384];           // h1 ring, fp16 A-fragment layout (64KB/slab)
__device__ uint32_t g_h2s[2 * 16384];           // h2 ring
struct alignas(128) Flag { unsigned v; unsigned pad[31]; };
__device__ Flag g_f1[TT + 2];
__device__ Flag g_f2[TT + 2];

// ---------------- helpers ----------------
__device__ __forceinline__ float tanha(float x) {
    float y;
    asm("tanh.approx.f32 %0, %1;" : "=f"(y) : "f"(x));
    return y;
}
__device__ __forceinline__ float sigm(float x) { return fmaf(tanha(0.5f * x), 0.5f, 0.5f); }

__device__ __forceinline__ uint32_t f2h2(float lo, float hi) {
    __half2 h = __floats2half2_rn(lo, hi);
    return *reinterpret_cast<uint32_t*>(&h);
}

__device__ __forceinline__ void mma16(float* d, uint4 a, uint32_t b0, uint32_t b1) {
    asm volatile(
        "mma.sync.aligned.m16n8k16.row.col.f32.f16.f16.f32 "
        "{%0,%1,%2,%3},{%4,%5,%6,%7},{%8,%9},{%0,%1,%2,%3};\n"
        : "+f"(d[0]), "+f"(d[1]), "+f"(d[2]), "+f"(d[3])
        : "r"(a.x), "r"(a.y), "r"(a.z), "r"(a.w), "r"(b0), "r"(b1));
}

__device__ __forceinline__ void waitflag(const unsigned* p, unsigned tgt) {
    unsigned v;
    do {
        asm volatile("ld.acquire.gpu.global.u32 %0, [%1];" : "=r"(v) : "l"(p) : "memory");
    } while (v < tgt);
}
__device__ __forceinline__ void waitflag2(const unsigned* p, unsigned tp,
                                          const unsigned* q, unsigned tq) {
    unsigned v, w;
    do {
        asm volatile("ld.acquire.gpu.global.u32 %0, [%1];" : "=r"(v) : "l"(p) : "memory");
        asm volatile("ld.acquire.gpu.global.u32 %0, [%1];" : "=r"(w) : "l"(q) : "memory");
    } while (v < tp || w < tq);
}

// CTA-wide wait: only tid 0 spins; the rest park on the barrier.
__device__ __forceinline__ void ctawait(const unsigned* p, unsigned tgt) {
    if (threadIdx.x == 0) waitflag(p, tgt);
    __syncthreads();
}
__device__ __forceinline__ void ctawait2(const unsigned* p, unsigned tp,
                                         const unsigned* q, unsigned tq) {
    if (threadIdx.x == 0) waitflag2(p, tp, q, tq);
    __syncthreads();
}

// 16 k16-tiles (K=256): A uint4 frags from gmem, B from smem.
__device__ __forceinline__ void gemm16(float acc[4][4], const uint4* __restrict__ Ap,
                                       const uint4* __restrict__ Bp) {
    uint4 aq[8];
#pragma unroll
    for (int i = 0; i < 8; i++) aq[i] = __ldcg(Ap + i * 128);
#pragma unroll
    for (int i = 0; i < 16; i++) {
        uint4 av = aq[i & 7];
        uint4 q1 = Bp[i * 128];
        uint4 q2 = Bp[i * 128 + 32];
        if (i < 8) aq[i & 7] = __ldcg(Ap + (i + 8) * 128);
        mma16(acc[0], av, q1.x, q2.x);
        mma16(acc[1], av, q1.y, q2.y);
        mma16(acc[2], av, q1.z, q2.z);
        mma16(acc[3], av, q1.w, q2.w);
    }
}

// ---------------- setup kernels ----------------
__global__ void reset_kernel() {
    int idx = blockIdx.x * 256 + threadIdx.x;
    if (idx < TT + 2) {
        g_f1[idx].v = (idx == 0) ? 32u : 0u;
        g_f2[idx].v = (idx == 0) ? 32u : 0u;
    }
    if (idx < 16384) {
        g_h1s[3 * 16384 + idx] = 0u;   // h1[-1] slab
        g_h2s[16384 + idx] = 0u;       // h2[-1] slab
    }
}

__global__ void pack_kernel(const float* __restrict__ Whh0, const float* __restrict__ Wih1,
                            const float* __restrict__ Whh1, const float* __restrict__ bih1,
                            const float* __restrict__ bhh1) {
    int cb = blockIdx.x;
    if (cb < 32) {
        int c = cb;
        uint32_t* dst = g_wf1 + c * 16384;
        for (int idx = threadIdx.x; idx < 16384; idx += 256) {
            int e = idx & 3, lane = (idx >> 2) & 31, h = (idx >> 7) & 1;
            int ns = (idx >> 8) & 1, kt = idx >> 9;
            int gid = lane >> 2, tig = lane & 3;
            int r = e * 512 + c * 16 + ns * 8 + gid;
            int k = kt * 16 + h * 8 + tig * 2;
            dst[idx] = f2h2(Whh0[r * HH + k], Whh0[r * HH + k + 1]);
        }
    } else {
        int c = cb - 32;
        uint32_t* dst = g_wf2 + c * 32768;
        for (int idx = threadIdx.x; idx < 32768; idx += 256) {
            int e = idx & 3, lane = (idx >> 2) & 31, h = (idx >> 7) & 1;
            int ns = (idx >> 8) & 1, kt = idx >> 9;
            int gid = lane >> 2, tig = lane & 3;
            int r = e * 512 + c * 16 + ns * 8 + gid;
            float v0, v1;
            if (kt < 32) {
                int k = kt * 16 + h * 8 + tig * 2;
                v0 = Wih1[r * HH + k]; v1 = Wih1[r * HH + k + 1];
            } else {
                int k = (kt - 32) * 16 + h * 8 + tig * 2;
                v0 = Whh1[r * HH + k]; v1 = Whh1[r * HH + k + 1];
            }
            dst[idx] = f2h2(v0, v1);
        }
        for (int idx = threadIdx.x; idx < 4096; idx += 256) {
            int j = idx & 7, lane = (idx >> 3) & 31, ns = (idx >> 10) & 1;
            int r = (j >> 1) * 512 + c * 16 + ns * 8 + (lane & 3) * 2 + (j & 1);
            g_b2p[c * 4096 + idx] = bih1[r] + bhh1[r];
        }
    }
}

// acc-init for layer1 (rewritten: register-resident x, broadcast LDS.128 weights)
__global__ void xg0_kernel(const float* __restrict__ x, const float* __restrict__ Wih0,
                           const float* __restrict__ bih0, const float* __restrict__ bhh0) {
    __shared__ float ws[64][40];    // padded stride 40 -> aligned float4 rows
    __shared__ float gsm[64][65];   // [b][rl] gates tile
    __shared__ float bsm[64];
    int t = blockIdx.x >> 5, c = blockIdx.x & 31;
    int tid = threadIdx.x;
    for (int i = tid; i < 64 * FF; i += 256) {
        int rl = i / FF, f = i - rl * FF;
        int r = (rl >> 4) * 512 + c * 16 + (rl & 15);
        ws[rl][f] = Wih0[r * FF + f];
    }
    if (tid < 64) {
        int rl = tid;
        int r = (rl >> 4) * 512 + c * 16 + (rl & 15);
        bsm[rl] = bih0[r] + bhh0[r];
    }
    __syncthreads();
    // phase A: outer-product. b = tid&63 (uniform rq per warp -> ws reads broadcast)
    {
        int b = tid & 63, rq = tid >> 6;
        float xr[36];
        const float4* xp = (const float4*)(x + ((size_t)b * TT + t) * FF);
#pragma unroll
        for (int f4 = 0; f4 < 9; f4++) {
            float4 v = __ldg(xp + f4);
            xr[f4 * 4] = v.x; xr[f4 * 4 + 1] = v.y; xr[f4 * 4 + 2] = v.z; xr[f4 * 4 + 3] = v.w;
        }
#pragma unroll
        for (int jr = 0; jr < 16; jr++) {
            int rl = rq * 16 + jr;
            const float4* wp = (const float4*)(&ws[rl][0]);
            float acc = 0.f;
#pragma unroll
            for (int f4 = 0; f4 < 9; f4++) {
                float4 w = wp[f4];
                acc = fmaf(xr[f4 * 4], w.x, acc);
                acc = fmaf(xr[f4 * 4 + 1], w.y, acc);
                acc = fmaf(xr[f4 * 4 + 2], w.z, acc);
                acc = fmaf(xr[f4 * 4 + 3], w.w, acc);
            }
            gsm[b][rl] = acc;
        }
    }
    __syncthreads();
    // phase B: consumer-layout packing (original mapping, reading gsm)
    int ks = tid >> 7, ns = (tid >> 6) & 1;
    int sub = tid & 63, m2 = sub >> 5, lane = sub & 31;
    int gid = lane >> 2, tig = lane & 3;
#pragma unroll
    for (int mh = 0; mh < 2; mh++) {
        int mt = m2 + 2 * mh;
        int b = mt * 16 + gid + 8 * ks;
        float v[8];
#pragma unroll
        for (int j = 0; j < 8; j++) {
            int rl = (j >> 1) * 16 + ns * 8 + tig * 2 + (j & 1);
            v[j] = bsm[rl] + gsm[b][rl];
        }
        size_t off = (size_t)t * 131072 + c * 4096 + ks * 2048 + ns * 1024 + mt * 256 + (size_t)lane * 8;
        float4* op = (float4*)(g_xg0p + off);
        op[0] = make_float4(v[0], v[1], v[2], v[3]);
        op[1] = make_float4(v[4], v[5], v[6], v[7]);
    }
}

// ---------------- persistent 2-layer LSTM ----------------
#define SMEM_BYTES 147456

__global__ void __launch_bounds__(NT, 1) lstm_kernel() {
    extern __shared__ uint4 smemu[];
    uint4* Bs4 = smemu;
    float4* RA = (float4*)(smemu + 8192);
    float4* RB = RA + 512;

    const int cta = blockIdx.x;
    const int layer = cta >> 5;
    const int c = cta & 31;
    const int tid = threadIdx.x;
    const int ks = tid >> 8;
    const int ns = (tid >> 7) & 1;
    const int mt = (tid >> 5) & 3;
    const int lane = tid & 31;
    const int idx = (ns * 4 + mt) * 32 + lane;
    const size_t thrOff = c * 4096 + ks * 2048 + ns * 1024 + mt * 256 + (size_t)lane * 8;

    {   // weights -> smem (fragment-packed already)
        const uint4* wsrc = (const uint4*)(layer ? (g_wf2 + c * 32768) : (g_wf1 + c * 16384));
        int tot = layer ? 8192 : 4096;
        for (int i = tid; i < tot; i += NT) Bs4[i] = wsrc[i];
    }
    float cst0 = 0.f, cst1 = 0.f;
    __syncthreads();

    for (int t = 0; t < TT; t++) {
        float acc[4][4];
#pragma unroll
        for (int q = 0; q < 16; q++) acc[q >> 2][q & 3] = 0.f;
        float4 f4a, f4b;
        if (!layer) {
            const float4* xp = (const float4*)(g_xg0p + (size_t)t * 131072 + thrOff);
            f4a = __ldcg(xp); f4b = __ldcg(xp + 1);
            if (t >= 4) ctawait2(&g_f2[t - 3].v, 32, &g_f1[t].v, 32);
            else        ctawait(&g_f1[t].v, 32);
        } else {
            const float4* bp = (const float4*)(g_b2p + thrOff);
            f4a = bp[0]; f4b = bp[1];
        }
        if (ks == 0) {
            acc[0][0] = f4a.x; acc[0][1] = f4a.y; acc[1][0] = f4a.z; acc[1][1] = f4a.w;
            acc[2][0] = f4b.x; acc[2][1] = f4b.y; acc[3][0] = f4b.z; acc[3][1] = f4b.w;
        } else {
            acc[0][2] = f4a.x; acc[0][3] = f4a.y; acc[1][2] = f4a.z; acc[1][3] = f4a.w;
            acc[2][2] = f4b.x; acc[2][3] = f4b.y; acc[3][2] = f4b.z; acc[3][3] = f4b.w;
        }
        if (!layer) {
            const uint4* Ap = (const uint4*)(g_h1s + ((t - 1) & 3) * 16384) + ks * 2048 + mt * 32 + lane;
            gemm16(acc, Ap, Bs4 + ks * 2048 + ns * 64 + lane);
        } else {
            // REORDERED: h1-dependent GEMM first (h1[t] is ready early — layer1 runs ahead),
            // so the f2-critical chain is only ONE gemm16.
            ctawait(&g_f1[t + 1].v, 32);                                      // h1[t] ready
            const uint4* Ap1 = (const uint4*)(g_h1s + (t & 3) * 16384) + ks * 2048 + mt * 32 + lane;
            gemm16(acc, Ap1, Bs4 + ks * 2048 + ns * 64 + lane);               // W_ih1 half
            ctawait(&g_f2[t].v, 32);                                          // h2[t-1] — serial dep
            const uint4* Ap2 = (const uint4*)(g_h2s + ((t - 1) & 1) * 16384) + ks * 2048 + mt * 32 + lane;
            gemm16(acc, Ap2, Bs4 + (32 + ks * 16) * 128 + ns * 64 + lane);    // W_hh1 half
        }
        // k-split exchange (each group ships the p-half it doesn't own)
        float4 wa, wb;
        if (ks == 0) {
            wa = make_float4(acc[0][2], acc[0][3], acc[1][2], acc[1][3]);
            wb = make_float4(acc[2][2], acc[2][3], acc[3][2], acc[3][3]);
        } else {
            wa = make_float4(acc[0][0], acc[0][1], acc[1][0], acc[1][1]);
            wb = make_float4(acc[2][0], acc[2][1], acc[3][0], acc[3][1]);
        }
        RA[(ks ^ 1) * 256 + idx] = wa;
        RB[(ks ^ 1) * 256 + idx] = wb;
        __syncthreads();
        float4 fa = RA[ks * 256 + idx];
        float4 fb = RB[ks * 256 + idx];
        float gi0, gi1, gf0, gf1, gg0, gg1, go0, go1;
        if (ks == 0) {
            gi0 = acc[0][0] + fa.x; gi1 = acc[0][1] + fa.y;
            gf0 = acc[1][0] + fa.z; gf1 = acc[1][1] + fa.w;
            gg0 = acc[2][0] + fb.x; gg1 = acc[2][1] + fb.y;
            go0 = acc[3][0] + fb.z; go1 = acc[3][1] + fb.w;
        } else {
            gi0 = acc[0][2] + fa.x; gi1 = acc[0][3] + fa.y;
            gf0 = acc[1][2] + fa.z; gf1 = acc[1][3] + fa.w;
            gg0 = acc[2][2] + fb.x; gg1 = acc[2][3] + fb.y;
            go0 = acc[3][2] + fb.z; go1 = acc[3][3] + fb.w;
        }
        float cv0 = fmaf(sigm(gf0), cst0, sigm(gi0) * tanha(gg0));
        float cv1 = fmaf(sigm(gf1), cst1, sigm(gi1) * tanha(gg1));
        cst0 = cv0; cst1 = cv1;
        float h0 = sigm(go0) * tanha(cv0);
        float h1 = sigm(go1) * tanha(cv1);
        uint32_t hv = f2h2(h0, h1);
        uint32_t* slab = layer ? (g_h2s + (t & 1) * 16384) : (g_h1s + (t & 3) * 16384);
        slab[((c * 4 + mt) * 32 + lane) * 4 + ks + 2 * ns] = hv;
        __syncthreads();
        if (tid == 0) {
            unsigned* fp = layer ? &g_f2[t + 1].v : &g_f1[t + 1].v;
            asm volatile("red.release.gpu.global.add.u32 [%0], 1;" ::"l"(fp) : "memory");
        }
    }
}

// ---------------- final projection ----------------
__global__ void out_kernel(const float* __restrict__ Wout, const float* __restrict__ bout,
                           float* __restrict__ out) {
    __shared__ float hs[512];
    int b = blockIdx.x;
    int mt = b >> 4, ksb = (b >> 3) & 1, gid = b & 7;
    const uint32_t* slab = g_h2s + ((TT - 1) & 1) * 16384;
    for (int k = threadIdx.x; k < 512; k += 64) {
        int cc = k >> 4, ns = (k >> 3) & 1, tig = (k & 7) >> 1, par = k & 1;
        uint32_t v = slab[((cc * 4 + mt) * 32 + gid * 4 + tig) * 4 + ksb + 2 * ns];
        __half2 h2v = *reinterpret_cast<__half2*>(&v);
        hs[k] = par ? __high2float(h2v) : __low2float(h2v);
    }
    __syncthreads();
    int o = threadIdx.x;
    float acc = bout[o];
    const float* wr = Wout + o * HH;
#pragma unroll 8
    for (int k = 0; k < HH; k++) acc = fmaf(hs[k], wr[k], acc);
    out[b * 64 + o] = acc;
}

// ---------------- launch ----------------
extern "C" void kernel_launch(void* const* d_in, const int* in_sizes, int n_in,
                              void* d_out, int out_size) {
    const float* x    = (const float*)d_in[0];
    const float* Wih0 = (const float*)d_in[1];
    const float* Whh0 = (const float*)d_in[2];
    const float* bih0 = (const float*)d_in[3];
    const float* bhh0 = (const float*)d_in[4];
    const float* Wih1 = (const float*)d_in[5];
    const float* Whh1 = (const float*)d_in[6];
    const float* bih1 = (const float*)d_in[7];
    const float* bhh1 = (const float*)d_in[8];
    const float* Wout = (const float*)d_in[9];
    const float* bout = (const float*)d_in[10];
    float* out = (float*)d_out;

    cudaFuncSetAttribute(lstm_kernel, cudaFuncAttributeMaxDynamicSharedMemorySize, SMEM_BYTES);

    reset_kernel<<<64, 256>>>();
    pack_kernel<<<64, 256>>>(Whh0, Wih1, Whh1, bih1, bhh1);
    xg0_kernel<<<TT * 32, 256>>>(x, Wih0, bih0, bhh0);
    lstm_kernel<<<GRID, NT, SMEM_BYTES>>>();
    out_kernel<<<64, 64>>>(Wout, bout, out);
}

// round 9
// speedup vs baseline: 5.9963x; 1.3696x over previous
#include <cuda_runtime.h>
#include <cuda_fp16.h>
#include <cstdint>

#define BB 64
#define TT 1500
#define FF 36
#define HH 512
#define NT 256          // 8 warps: ks2 x mt4; each warp covers n=32 (8 units x 4 gates)
#define GRID 128        // 64 CTAs per layer, 8 units per CTA

// ---------------- device globals ----------------
__device__ float g_xg0p[(size_t)TT * 131072];   // 786MB acc-init [t][c64][tl128][q4][e4]
__device__ float g_b2p[64 * 2048];              // layer2 bias  [c][tl128][q4][e4]
__device__ uint32_t g_wf1[64 * 8192];           // layer1 B-frags [c][kt32][p2][lane32][e4]
__device__ uint32_t g_wf2[64 * 16384];          // layer2 B-frags [c][kt64][p2][lane32][e4]
__device__ uint32_t g_h1s[4 * 16384];           // h1 ring, fp16 A-frag layout [kt16][mt4][lane32][reg4]
__device__ uint32_t g_h2s[2 * 16384];           // h2 ring
struct alignas(128) Flag { unsigned v; unsigned pad[31]; };
__device__ Flag g_f1[TT + 2];
__device__ Flag g_f2[TT + 2];

// ---------------- helpers ----------------
__device__ __forceinline__ float tanha(float x) {
    float y;
    asm("tanh.approx.f32 %0, %1;" : "=f"(y) : "f"(x));
    return y;
}
__device__ __forceinline__ float sigm(float x) { return fmaf(tanha(0.5f * x), 0.5f, 0.5f); }

__device__ __forceinline__ uint32_t f2h2(float lo, float hi) {
    __half2 h = __floats2half2_rn(lo, hi);
    return *reinterpret_cast<uint32_t*>(&h);
}

__device__ __forceinline__ void mma16(float* d, uint4 a, uint32_t b0, uint32_t b1) {
    asm volatile(
        "mma.sync.aligned.m16n8k16.row.col.f32.f16.f16.f32 "
        "{%0,%1,%2,%3},{%4,%5,%6,%7},{%8,%9},{%0,%1,%2,%3};\n"
        : "+f"(d[0]), "+f"(d[1]), "+f"(d[2]), "+f"(d[3])
        : "r"(a.x), "r"(a.y), "r"(a.z), "r"(a.w), "r"(b0), "r"(b1));
}

__device__ __forceinline__ void waitflag(const unsigned* p, unsigned tgt) {
    unsigned v;
    do {
        asm volatile("ld.acquire.gpu.global.u32 %0, [%1];" : "=r"(v) : "l"(p) : "memory");
    } while (v < tgt);
}
__device__ __forceinline__ void waitflag2(const unsigned* p, unsigned tp,
                                          const unsigned* q, unsigned tq) {
    unsigned v, w;
    do {
        asm volatile("ld.acquire.gpu.global.u32 %0, [%1];" : "=r"(v) : "l"(p) : "memory");
        asm volatile("ld.acquire.gpu.global.u32 %0, [%1];" : "=r"(w) : "l"(q) : "memory");
    } while (v < tp || w < tq);
}
__device__ __forceinline__ void ctawait(const unsigned* p, unsigned tgt) {
    if (threadIdx.x == 0) waitflag(p, tgt);
    __syncthreads();
}
__device__ __forceinline__ void ctawait2(const unsigned* p, unsigned tp,
                                         const unsigned* q, unsigned tq) {
    if (threadIdx.x == 0) waitflag2(p, tp, q, tq);
    __syncthreads();
}

// 16 k16-tiles (K=256 half): per kt: 1 LDG.128 (A) + 2 LDS.128 (B, 4 n-tiles) + 4 MMA.
__device__ __forceinline__ void gemm16b(float acc[4][4], const uint4* __restrict__ Ap,
                                        const uint4* __restrict__ Bp) {
    uint4 aq[8];
#pragma unroll
    for (int i = 0; i < 8; i++) aq[i] = __ldcg(Ap + i * 128);
#pragma unroll
    for (int i = 0; i < 16; i++) {
        uint4 av = aq[i & 7];
        uint4 q1 = Bp[i * 64];
        uint4 q2 = Bp[i * 64 + 32];
        if (i < 8) aq[i & 7] = __ldcg(Ap + (i + 8) * 128);
        mma16(acc[0], av, q1.x, q1.y);
        mma16(acc[1], av, q1.z, q1.w);
        mma16(acc[2], av, q2.x, q2.y);
        mma16(acc[3], av, q2.z, q2.w);
    }
}

// ---------------- setup kernels ----------------
__global__ void reset_kernel() {
    int idx = blockIdx.x * 256 + threadIdx.x;
    if (idx < TT + 2) {
        g_f1[idx].v = (idx == 0) ? 64u : 0u;
        g_f2[idx].v = (idx == 0) ? 64u : 0u;
    }
    if (idx < 16384) {
        g_h1s[3 * 16384 + idx] = 0u;   // h1[-1] slab ((-1)&3 = 3)
        g_h2s[16384 + idx] = 0u;       // h2[-1] slab ((-1)&1 = 1)
    }
}

// B-fragment value for (c, kt-global within source W, p, lane, e):
//   nt = 2p + (e>>1); gate = (nt&1)*2 + (gid&1); u = c*8 + (nt>>1)*4 + (gid>>1)
//   row = gate*512 + u; k = kt*16 + (e&1)*8 + tig*2
__global__ void pack_kernel(const float* __restrict__ Whh0, const float* __restrict__ Wih1,
                            const float* __restrict__ Whh1, const float* __restrict__ bih1,
                            const float* __restrict__ bhh1) {
    int cb = blockIdx.x;
    if (cb < 64) {
        int c = cb;
        uint32_t* dst = g_wf1 + c * 8192;
        for (int idx = threadIdx.x; idx < 8192; idx += 256) {
            int e = idx & 3, lane = (idx >> 2) & 31, p = (idx >> 7) & 1, kt = idx >> 8;
            int gid = lane >> 2, tig = lane & 3;
            int nt = 2 * p + (e >> 1);
            int gate = (nt & 1) * 2 + (gid & 1);
            int u = c * 8 + (nt >> 1) * 4 + (gid >> 1);
            int row = gate * 512 + u;
            int k = kt * 16 + (e & 1) * 8 + tig * 2;
            dst[idx] = f2h2(Whh0[row * HH + k], Whh0[row * HH + k + 1]);
        }
    } else {
        int c = cb - 64;
        uint32_t* dst = g_wf2 + c * 16384;
        for (int idx = threadIdx.x; idx < 16384; idx += 256) {
            int e = idx & 3, lane = (idx >> 2) & 31, p = (idx >> 7) & 1, kt = idx >> 8;
            int gid = lane >> 2, tig = lane & 3;
            int nt = 2 * p + (e >> 1);
            int gate = (nt & 1) * 2 + (gid & 1);
            int u = c * 8 + (nt >> 1) * 4 + (gid >> 1);
            int row = gate * 512 + u;
            float v0, v1;
            if (kt < 32) {
                int k = kt * 16 + (e & 1) * 8 + tig * 2;
                v0 = Wih1[row * HH + k]; v1 = Wih1[row * HH + k + 1];
            } else {
                int k = (kt - 32) * 16 + (e & 1) * 8 + tig * 2;
                v0 = Whh1[row * HH + k]; v1 = Whh1[row * HH + k + 1];
            }
            dst[idx] = f2h2(v0, v1);
        }
        // bias in acc-slot layout: [tl128][q4][e4]; gate=(q&1)*2+(e&1); u=c*8+(q>>1)*4+tig
        for (int idx = threadIdx.x; idx < 2048; idx += 256) {
            int e = idx & 3, q = (idx >> 2) & 3, tl = idx >> 4;
            int tig = tl & 3;
            int u = c * 8 + (q >> 1) * 4 + tig;
            int gate = (q & 1) * 2 + (e & 1);
            int row = gate * 512 + u;
            g_b2p[c * 2048 + idx] = bih1[row] + bhh1[row];
        }
    }
}

// acc-init for layer1 in the same acc-slot layout
__global__ void xg0_kernel(const float* __restrict__ x, const float* __restrict__ Wih0,
                           const float* __restrict__ bih0, const float* __restrict__ bhh0) {
    __shared__ float ws[32][40];    // rows rl = gate*8 + uloc
    __shared__ float gsm[64][33];   // [b][rl]
    __shared__ float bsm[32];
    int t = blockIdx.x >> 6, c = blockIdx.x & 63;
    int tid = threadIdx.x;
    for (int i = tid; i < 32 * FF; i += 256) {
        int rl = i / FF, f = i - rl * FF;
        int row = (rl >> 3) * 512 + c * 8 + (rl & 7);
        ws[rl][f] = Wih0[row * FF + f];
    }
    if (tid < 32) {
        int rl = tid;
        int row = (rl >> 3) * 512 + c * 8 + (rl & 7);
        bsm[rl] = bih0[row] + bhh0[row];
    }
    __syncthreads();
    {   // phase A: outer product, x in registers, ws broadcast per warp
        int b = tid & 63, rq = tid >> 6;
        float xr[36];
        const float4* xp = (const float4*)(x + ((size_t)b * TT + t) * FF);
#pragma unroll
        for (int f4 = 0; f4 < 9; f4++) {
            float4 v = __ldg(xp + f4);
            xr[f4 * 4] = v.x; xr[f4 * 4 + 1] = v.y; xr[f4 * 4 + 2] = v.z; xr[f4 * 4 + 3] = v.w;
        }
#pragma unroll
        for (int jr = 0; jr < 8; jr++) {
            int rl = rq * 8 + jr;
            const float4* wp = (const float4*)(&ws[rl][0]);
            float a = 0.f;
#pragma unroll
            for (int f4 = 0; f4 < 9; f4++) {
                float4 w = wp[f4];
                a = fmaf(xr[f4 * 4], w.x, a);
                a = fmaf(xr[f4 * 4 + 1], w.y, a);
                a = fmaf(xr[f4 * 4 + 2], w.z, a);
                a = fmaf(xr[f4 * 4 + 3], w.w, a);
            }
            gsm[b][rl] = a;
        }
    }
    __syncthreads();
    {   // phase B: acc-slot packing (2 quads per thread)
        int hq = tid >> 7, tl = tid & 127;
        int mtb = tl >> 5, lane = tl & 31;
        int gid = lane >> 2, tig = lane & 3;
        float v[8];
#pragma unroll
        for (int qq = 0; qq < 2; qq++) {
            int q = hq * 2 + qq;
            int uloc = (q >> 1) * 4 + tig;
#pragma unroll
            for (int e = 0; e < 4; e++) {
                int gate = (q & 1) * 2 + (e & 1);
                int b = mtb * 16 + gid + 8 * (e >> 1);
                v[qq * 4 + e] = bsm[gate * 8 + uloc] + gsm[b][gate * 8 + uloc];
            }
        }
        size_t off = (size_t)t * 131072 + c * 2048 + tl * 16 + hq * 8;
        float4* op = (float4*)(g_xg0p + off);
        op[0] = make_float4(v[0], v[1], v[2], v[3]);
        op[1] = make_float4(v[4], v[5], v[6], v[7]);
    }
}

// ---------------- persistent 2-layer LSTM ----------------
// smem: Bs uint4[4096] (64KB weights) + EX float4[512] (8KB k-split handoff)
#define SMEM_BYTES 73728

__global__ void __launch_bounds__(NT, 1) lstm_kernel() {
    extern __shared__ uint4 smemu[];
    uint4* Bs = smemu;
    float4* EX = (float4*)(smemu + 4096);

    const int cta = blockIdx.x;
    const int layer = cta >> 6;
    const int c = cta & 63;
    const int tid = threadIdx.x;
    const int ks = tid >> 7;               // k-split group
    const int tl = tid & 127;
    const int mt = (tid >> 5) & 3;
    const int lane = tid & 31;
    const int gid = lane >> 2, tig = lane & 3;

    {   // weights -> smem (fragment-packed)
        const uint4* wsrc = (const uint4*)(layer ? (g_wf2 + c * 16384) : (g_wf1 + c * 8192));
        int tot = layer ? 4096 : 2048;
        for (int i = tid; i < tot; i += NT) Bs[i] = wsrc[i];
    }
    float bias16[16];
    if (layer && ks == 0) {
        const float4* bp = (const float4*)(g_b2p + c * 2048 + tl * 16);
#pragma unroll
        for (int q = 0; q < 4; q++) {
            float4 v = bp[q];
            bias16[q * 4] = v.x; bias16[q * 4 + 1] = v.y;
            bias16[q * 4 + 2] = v.z; bias16[q * 4 + 3] = v.w;
        }
    }
    float cst[4] = {0.f, 0.f, 0.f, 0.f};
    __syncthreads();

    // h-store addressing (ks0 threads): units u1=c*8+tig, u2=c*8+4+tig; batches mt*16+gid, +8
    const int ktS = c >> 1;
    const int sbase = ((ktS * 4 + mt) * 32 + gid * 4 + (tig >> 1)) * 4 + 2 * (c & 1);
    const int half = tig & 1;

    for (int t = 0; t < TT; t++) {
        float acc[4][4];
        if (!layer) {
            float4 xg[4];
            if (ks == 0) {
                const float4* xp = (const float4*)(g_xg0p + (size_t)t * 131072 + c * 2048 + tl * 16);
#pragma unroll
                for (int q = 0; q < 4; q++) xg[q] = __ldcg(xp + q);
            }
            if (t >= 4) ctawait2(&g_f2[t - 3].v, 64, &g_f1[t].v, 64);
            else        ctawait(&g_f1[t].v, 64);
            if (ks == 0) {
#pragma unroll
                for (int q = 0; q < 4; q++) {
                    acc[q][0] = xg[q].x; acc[q][1] = xg[q].y;
                    acc[q][2] = xg[q].z; acc[q][3] = xg[q].w;
                }
            } else {
#pragma unroll
                for (int i = 0; i < 16; i++) acc[i >> 2][i & 3] = 0.f;
            }
            const uint4* Ap = (const uint4*)(g_h1s + ((t - 1) & 3) * 16384) + ks * 2048 + mt * 32 + lane;
            gemm16b(acc, Ap, Bs + ks * 1024 + lane);
        } else {
            if (ks == 0) {
#pragma unroll
                for (int i = 0; i < 16; i++) acc[i >> 2][i & 3] = bias16[i];
            } else {
#pragma unroll
                for (int i = 0; i < 16; i++) acc[i >> 2][i & 3] = 0.f;
            }
            ctawait(&g_f1[t + 1].v, 64);   // h1[t] ready (layer1 runs ahead)
            const uint4* Ap1 = (const uint4*)(g_h1s + (t & 3) * 16384) + ks * 2048 + mt * 32 + lane;
            gemm16b(acc, Ap1, Bs + ks * 1024 + lane);                 // W_ih1 part
            ctawait(&g_f2[t].v, 64);       // h2[t-1] — the serial dependence
            const uint4* Ap2 = (const uint4*)(g_h2s + ((t - 1) & 1) * 16384) + ks * 2048 + mt * 32 + lane;
            gemm16b(acc, Ap2, Bs + 2048 + ks * 1024 + lane);          // W_hh1 part
        }
        // k-split handoff: ks1 ships all partials; ks0 reduces, does cell + h store
        if (ks == 1) {
#pragma unroll
            for (int q = 0; q < 4; q++)
                EX[tl * 4 + q] = make_float4(acc[q][0], acc[q][1], acc[q][2], acc[q][3]);
        }
        __syncthreads();
        uint32_t* slab = layer ? (g_h2s + (t & 1) * 16384) : (g_h1s + (t & 3) * 16384);
        if (ks == 0) {
#pragma unroll
            for (int q = 0; q < 4; q++) {
                float4 v = EX[tl * 4 + q];
                acc[q][0] += v.x; acc[q][1] += v.y; acc[q][2] += v.z; acc[q][3] += v.w;
            }
            uint16_t* hp = (uint16_t*)slab;
#pragma unroll
            for (int uu = 0; uu < 2; uu++) {
#pragma unroll
                for (int bb = 0; bb < 2; bb++) {
                    float iv = sigm(acc[uu * 2][bb * 2]);
                    float fv = sigm(acc[uu * 2][bb * 2 + 1]);
                    float gv = tanha(acc[uu * 2 + 1][bb * 2]);
                    float ov = sigm(acc[uu * 2 + 1][bb * 2 + 1]);
                    int ci = uu * 2 + bb;
                    float cv = fmaf(fv, cst[ci], iv * gv);
                    cst[ci] = cv;
                    float hv = ov * tanha(cv);
                    __half hh = __float2half_rn(hv);
                    hp[(sbase + uu * 8 + bb) * 2 + half] = __half_as_ushort(hh);
                }
            }
        }
        __syncthreads();
        if (tid == 0) {
            unsigned* fp = layer ? &g_f2[t + 1].v : &g_f1[t + 1].v;
            asm volatile("red.release.gpu.global.add.u32 [%0], 1;" ::"l"(fp) : "memory");
        }
    }
}

// ---------------- final projection ----------------
__global__ void out_kernel(const float* __restrict__ Wout, const float* __restrict__ bout,
                           float* __restrict__ out) {
    __shared__ float hs[512];
    int b = blockIdx.x;
    const uint32_t* slab = g_h2s + ((TT - 1) & 1) * 16384;
    for (int k = threadIdx.x; k < 512; k += 64) {
        int kt = k >> 4, ku = k & 15, mtb = b >> 4, r = b & 15;
        int laneS = (r & 7) * 4 + ((ku & 7) >> 1);
        int reg = (r >> 3) + 2 * (ku >> 3);
        uint32_t v = slab[((kt * 4 + mtb) * 32 + laneS) * 4 + reg];
        __half2 h2v = *reinterpret_cast<__half2*>(&v);
        hs[k] = (ku & 1) ? __high2float(h2v) : __low2float(h2v);
    }
    __syncthreads();
    int o = threadIdx.x;
    float acc = bout[o];
    const float* wr = Wout + o * HH;
#pragma unroll 8
    for (int k = 0; k < HH; k++) acc = fmaf(hs[k], wr[k], acc);
    out[b * 64 + o] = acc;
}

// ---------------- launch ----------------
extern "C" void kernel_launch(void* const* d_in, const int* in_sizes, int n_in,
                              void* d_out, int out_size) {
    const float* x    = (const float*)d_in[0];
    const float* Wih0 = (const float*)d_in[1];
    const float* Whh0 = (const float*)d_in[2];
    const float* bih0 = (const float*)d_in[3];
    const float* bhh0 = (const float*)d_in[4];
    const float* Wih1 = (const float*)d_in[5];
    const float* Whh1 = (const float*)d_in[6];
    const float* bih1 = (const float*)d_in[7];
    const float* bhh1 = (const float*)d_in[8];
    const float* Wout = (const float*)d_in[9];
    const float* bout = (const float*)d_in[10];
    float* out = (float*)d_out;

    cudaFuncSetAttribute(lstm_kernel, cudaFuncAttributeMaxDynamicSharedMemorySize, SMEM_BYTES);

    reset_kernel<<<64, 256>>>();
    pack_kernel<<<128, 256>>>(Whh0, Wih1, Whh1, bih1, bhh1);
    xg0_kernel<<<TT * 64, 256>>>(x, Wih0, bih0, bhh0);
    lstm_kernel<<<GRID, NT, SMEM_BYTES>>>();
    out_kernel<<<64, 64>>>(Wout, bout, out);
}